// round 10
// baseline (speedup 1.0000x reference)
#include <cuda_runtime.h>
#include <cuda_fp16.h>
#include <cstdint>

// Problem constants (fixed shapes)
#define NN 50000
#define EE 1600000
#define IN_DIM 256
#define HC 128          // H*C = 4*32
#define OUT_DIM 64
#define NEG_SLOPE 0.2f
#define SCAN_NBLK 49    // ceil(50000/1024)
#define G1BLK 782       // gemm1 blocks  (ceil(50000/64))
#define HISTBLK 6250    // hist blocks   (EE/256)
#define ATTNBLK 1563    // attn blocks   (ceil(50000/32) nodes @32 warps/blk)

// ---------------- scratch (__device__ globals; no allocation allowed) -------
__device__ float  g_h[(size_t)NN * HC];    // x @ W (fp32)
__device__ __half g_h16[(size_t)NN * HC];  // fp16 shadow for the gather path
__device__ float  g_asrc[NN * 4];
__device__ float  g_adst[NN * 4];
__device__ float  g_z[(size_t)NN * HC];    // elu(agg + bias)
__device__ int    g_cnt[NN];
__device__ int    g_off[NN + 1];
__device__ int    g_bsum[64];
__device__ int    g_srcsorted[EE];

// ---------------- f32x2 packed FMA helpers (sm_103a FFMA2) -------------------
__device__ __forceinline__ unsigned long long pack2(float lo, float hi)
{
    unsigned long long r;
    asm("mov.b64 %0, {%1, %2};" : "=l"(r) : "f"(lo), "f"(hi));
    return r;
}
__device__ __forceinline__ void unpack2(unsigned long long v, float& lo, float& hi)
{
    asm("mov.b64 {%0, %1}, %2;" : "=f"(lo), "=f"(hi) : "l"(v));
}
__device__ __forceinline__ unsigned long long ffma2(unsigned long long a,
                                                    unsigned long long b,
                                                    unsigned long long c)
{
    unsigned long long d;
    asm("fma.rn.f32x2 %0, %1, %2, %3;" : "=l"(d) : "l"(a), "l"(b), "l"(c));
    return d;
}

// ---------------- per-block edge dtype detection ------------------------------
// int64 little-endian values < 2^31: odd int32 words are all zero.
__device__ __forceinline__ int block_detect_is64(const int* __restrict__ ei32)
{
    int any = 0;
    if (threadIdx.x < 64) any = ei32[2 * threadIdx.x + 1];
    return __syncthreads_or(any) ? 0 : 1;
}

__device__ __forceinline__ int load_edge(const void* ei, size_t idx, int is64)
{
    if (is64) return (int)((const long long*)ei)[idx];
    return ((const int*)ei)[idx];
}

// ---------------- fused1: gemm1 tiles  ||  hist -------------------------------
// gemm1: BM=64, BN=128, BK=32, 256 threads; M-paired FFMA2 accumulators.
__global__ void fused1_kernel(const float* __restrict__ x,
                              const float* __restrict__ W,
                              const void* __restrict__ ei)
{
    if (blockIdx.x >= G1BLK) {
        // ---- hist path ----
        int is64 = block_detect_is64((const int*)ei);
        int e = (blockIdx.x - G1BLK) * 256 + threadIdx.x;
        if (e < EE) {
            int d = load_edge(ei, (size_t)EE + e, is64);
            if ((unsigned)d < NN) atomicAdd(&g_cnt[d], 1);
        }
        return;
    }
    // ---- gemm1 path ----
    __shared__ float As[32][64];    // [k][m]
    __shared__ float Bs[32][128];   // [k][n]
    const int tid = threadIdx.x;
    const int tx = tid & 31;        // cols tx*4 .. tx*4+3
    const int ty = tid >> 5;        // rows ty*8 .. ty*8+7
    const int bm = blockIdx.x * 64;

    // acc2[ip][j]: row-pair (ty*8+2ip, ty*8+2ip+1), col tx*4+j
    unsigned long long acc2[4][4];
#pragma unroll
    for (int i = 0; i < 4; ++i)
#pragma unroll
        for (int jx = 0; jx < 4; ++jx) acc2[i][jx] = 0ull;

    for (int k0 = 0; k0 < IN_DIM; k0 += 32) {
#pragma unroll
        for (int r = 0; r < 2; ++r) {
            int idx = tid + r * 256;
            int row = idx >> 3;
            int kk4 = idx & 7;
            int gm = bm + row;
            float4 v = make_float4(0.f, 0.f, 0.f, 0.f);
            if (gm < NN)
                v = *reinterpret_cast<const float4*>(x + (size_t)gm * IN_DIM + k0 + kk4 * 4);
            As[kk4 * 4 + 0][row] = v.x;
            As[kk4 * 4 + 1][row] = v.y;
            As[kk4 * 4 + 2][row] = v.z;
            As[kk4 * 4 + 3][row] = v.w;
        }
#pragma unroll
        for (int r = 0; r < 4; ++r) {
            int idx = tid + r * 256;
            int kk = idx >> 5;
            int nn4 = idx & 31;
            *reinterpret_cast<float4*>(&Bs[kk][nn4 * 4]) =
                *reinterpret_cast<const float4*>(W + (size_t)(k0 + kk) * HC + nn4 * 4);
        }
        __syncthreads();
#pragma unroll
        for (int k = 0; k < 32; ++k) {
            // A row-pairs: direct 8-byte LDS -> register pair, warp-broadcast
            unsigned long long ap[4];
#pragma unroll
            for (int ip = 0; ip < 4; ++ip)
                ap[ip] = *reinterpret_cast<const unsigned long long*>(&As[k][ty * 8 + 2 * ip]);
            float4 bv = reinterpret_cast<const float4*>(&Bs[k][0])[tx];
            unsigned long long bd[4];
            bd[0] = pack2(bv.x, bv.x);
            bd[1] = pack2(bv.y, bv.y);
            bd[2] = pack2(bv.z, bv.z);
            bd[3] = pack2(bv.w, bv.w);
#pragma unroll
            for (int ip = 0; ip < 4; ++ip)
#pragma unroll
                for (int jx = 0; jx < 4; ++jx)
                    acc2[ip][jx] = ffma2(ap[ip], bd[jx], acc2[ip][jx]);
        }
        __syncthreads();
    }
#pragma unroll
    for (int ip = 0; ip < 4; ++ip) {
        float lo0, hi0, lo1, hi1, lo2, hi2, lo3, hi3;
        unpack2(acc2[ip][0], lo0, hi0);
        unpack2(acc2[ip][1], lo1, hi1);
        unpack2(acc2[ip][2], lo2, hi2);
        unpack2(acc2[ip][3], lo3, hi3);
        int gm0 = bm + ty * 8 + 2 * ip;
        int gm1 = gm0 + 1;
        if (gm0 < NN) {
            float4 o = make_float4(lo0, lo1, lo2, lo3);
            *reinterpret_cast<float4*>(g_h + (size_t)gm0 * HC + tx * 4) = o;
            __half2 h01 = __floats2half2_rn(o.x, o.y);
            __half2 h23 = __floats2half2_rn(o.z, o.w);
            *reinterpret_cast<__half2*>(g_h16 + (size_t)gm0 * HC + tx * 4 + 0) = h01;
            *reinterpret_cast<__half2*>(g_h16 + (size_t)gm0 * HC + tx * 4 + 2) = h23;
        }
        if (gm1 < NN) {
            float4 o = make_float4(hi0, hi1, hi2, hi3);
            *reinterpret_cast<float4*>(g_h + (size_t)gm1 * HC + tx * 4) = o;
            __half2 h01 = __floats2half2_rn(o.x, o.y);
            __half2 h23 = __floats2half2_rn(o.z, o.w);
            *reinterpret_cast<__half2*>(g_h16 + (size_t)gm1 * HC + tx * 4 + 0) = h01;
            *reinterpret_cast<__half2*>(g_h16 + (size_t)gm1 * HC + tx * 4 + 2) = h23;
        }
    }
}

// ---------------- fused2: scan1 (warp-shuffle)  ||  attn_halves ---------------
__global__ void fused2_kernel(const float* __restrict__ att_src,
                              const float* __restrict__ att_dst)
{
    if (blockIdx.x < SCAN_NBLK) {
        __shared__ int wsum[32];
        int t = threadIdx.x;
        int lane = t & 31;
        int wid = t >> 5;
        int i = blockIdx.x * 1024 + t;
        int v = (i < NN) ? g_cnt[i] : 0;
        int sc = v;
#pragma unroll
        for (int off = 1; off < 32; off <<= 1) {
            int n = __shfl_up_sync(0xFFFFFFFFu, sc, off);
            if (lane >= off) sc += n;
        }
        if (lane == 31) wsum[wid] = sc;
        __syncthreads();
        if (wid == 0) {
            int ws = wsum[lane];
#pragma unroll
            for (int off = 1; off < 32; off <<= 1) {
                int n = __shfl_up_sync(0xFFFFFFFFu, ws, off);
                if (lane >= off) ws += n;
            }
            wsum[lane] = ws;
        }
        __syncthreads();
        int base = (wid > 0) ? wsum[wid - 1] : 0;
        int inc = base + sc;
        if (i < NN) g_off[i + 1] = inc;
        if (t == 1023) g_bsum[blockIdx.x] = inc;
        return;
    }
    // ---- attn path ----
    int w = (blockIdx.x - SCAN_NBLK) * 32 + (threadIdx.x >> 5);
    int lane = threadIdx.x & 31;
    if (w >= NN) return;
    float4 hv = *reinterpret_cast<const float4*>(g_h + (size_t)w * HC + lane * 4);
    float4 s4 = *reinterpret_cast<const float4*>(att_src + lane * 4);
    float4 d4 = *reinterpret_cast<const float4*>(att_dst + lane * 4);
    float ps = hv.x * s4.x + hv.y * s4.y + hv.z * s4.z + hv.w * s4.w;
    float pd = hv.x * d4.x + hv.y * d4.y + hv.z * d4.z + hv.w * d4.w;
#pragma unroll
    for (int off = 1; off < 8; off <<= 1) {
        ps += __shfl_xor_sync(0xFFFFFFFFu, ps, off);
        pd += __shfl_xor_sync(0xFFFFFFFFu, pd, off);
    }
    float4 po, qo;
    po.x = __shfl_sync(0xFFFFFFFFu, ps, 0);
    po.y = __shfl_sync(0xFFFFFFFFu, ps, 8);
    po.z = __shfl_sync(0xFFFFFFFFu, ps, 16);
    po.w = __shfl_sync(0xFFFFFFFFu, ps, 24);
    qo.x = __shfl_sync(0xFFFFFFFFu, pd, 0);
    qo.y = __shfl_sync(0xFFFFFFFFu, pd, 8);
    qo.z = __shfl_sync(0xFFFFFFFFu, pd, 16);
    qo.w = __shfl_sync(0xFFFFFFFFu, pd, 24);
    if (lane == 0) {
        *reinterpret_cast<float4*>(g_asrc + w * 4) = po;
        *reinterpret_cast<float4*>(g_adst + w * 4) = qo;
    }
}

// ---------------- scan3: add cross-block prefix -------------------------------
__global__ void scan3_kernel()
{
    __shared__ int s_pref;
    if (threadIdx.x == 0) {
        int acc = 0;
        for (int b = 0; b < (int)blockIdx.x; ++b) acc += g_bsum[b];
        s_pref = acc;
    }
    __syncthreads();
    int i = blockIdx.x * 1024 + threadIdx.x;
    if (i < NN) g_off[i + 1] += s_pref;
    if (i == 0) g_off[0] = 0;
}

// ---------------- scatter: count-down slot assignment -------------------------
__global__ void scatter_kernel(const void* __restrict__ ei)
{
    int is64 = block_detect_is64((const int*)ei);
    int e = blockIdx.x * 256 + threadIdx.x;
    if (e < EE) {
        int d = load_edge(ei, (size_t)EE + e, is64);
        int s = load_edge(ei, (size_t)e, is64);
        if ((unsigned)d < NN && (unsigned)s < NN) {
            int rem = atomicSub(&g_cnt[d], 1);          // old count
            int pos = g_off[d] + rem - 1;
            if ((unsigned)pos < EE) g_srcsorted[pos] = s;
        }
    }
}

// ---------------- aggregation: warp per dst node, software-pipelined ----------
// Softmax without max-shift (logits bounded, shift-invariant => exact).
// Logit role:     lane = j*4 + kl  (j = edge slot 0..7, kl = head)
// Accumulate role: lane owns channels lane*4..lane*4+3, head kh = lane>>3
__global__ void agg_kernel(const float* __restrict__ bias)
{
    int w = (blockIdx.x * blockDim.x + threadIdx.x) >> 5;
    int lane = threadIdx.x & 31;
    if (w >= NN) return;
    const int kl = lane & 3;
    const int j  = lane >> 2;
    const int kh = lane >> 3;

    float adv_l = g_adst[w * 4 + kl];
    float asl_l = g_asrc[w * 4 + kl];
    float adv_a = g_adst[w * 4 + kh];
    float asl_a = g_asrc[w * 4 + kh];

    // self-loop contribution (fp32 h)
    float e0l = asl_l + adv_l;
    e0l = (e0l > 0.f) ? e0l : NEG_SLOPE * e0l;
    float dnm = (j == 0) ? __expf(e0l) : 0.f;

    float e0a = asl_a + adv_a;
    e0a = (e0a > 0.f) ? e0a : NEG_SLOPE * e0a;
    float pe0a = __expf(e0a);
    float4 hw = *reinterpret_cast<const float4*>(g_h + (size_t)w * HC + lane * 4);
    float4 acc;
    acc.x = pe0a * hw.x; acc.y = pe0a * hw.y;
    acc.z = pe0a * hw.z; acc.w = pe0a * hw.w;

    const int beg = g_off[w];
    const int end = g_off[w + 1];
    int p = beg;

    // software pipeline: prefetch next block's src index + attention half
    int   s_cur = 0;
    float as_cur = 0.f;
    if (p + 8 <= end) {
        s_cur  = g_srcsorted[p + j];
        as_cur = __ldg(g_asrc + (size_t)s_cur * 4 + kl);
    }
    while (p + 8 <= end) {
        const int p_next = p + 8;
        int   s_next = 0;
        float as_next = 0.f;
        if (p_next + 8 <= end) {
            s_next  = g_srcsorted[p_next + j];
            as_next = __ldg(g_asrc + (size_t)s_next * 4 + kl);
        }
        float e = as_cur + adv_l;
        e = (e > 0.f) ? e : NEG_SLOPE * e;
        float pe = __expf(e);
        dnm += pe;
#pragma unroll
        for (int jj = 0; jj < 8; ++jj) {
            int   sj = __shfl_sync(0xFFFFFFFFu, s_cur, jj * 4);
            float q  = __shfl_sync(0xFFFFFFFFu, pe,    jj * 4 + kh);
            const __half2* hp = reinterpret_cast<const __half2*>(
                g_h16 + (size_t)sj * HC + lane * 4);
            __half2 h01 = __ldg(hp + 0);
            __half2 h23 = __ldg(hp + 1);
            float2 f01 = __half22float2(h01);
            float2 f23 = __half22float2(h23);
            acc.x = fmaf(q, f01.x, acc.x);
            acc.y = fmaf(q, f01.y, acc.y);
            acc.z = fmaf(q, f23.x, acc.z);
            acc.w = fmaf(q, f23.y, acc.w);
        }
        s_cur = s_next;
        as_cur = as_next;
        p = p_next;
    }
    if (p < end) {
        int cnt = end - p;
        int ridx = p + ((j < cnt) ? j : (cnt - 1));
        int s = g_srcsorted[ridx];
        float as = __ldg(g_asrc + (size_t)s * 4 + kl);
        float e = as + adv_l;
        e = (e > 0.f) ? e : NEG_SLOPE * e;
        float pe = (j < cnt) ? __expf(e) : 0.f;
        dnm += pe;
        for (int jj = 0; jj < cnt; ++jj) {
            int   sj = __shfl_sync(0xFFFFFFFFu, s,  jj * 4);
            float q  = __shfl_sync(0xFFFFFFFFu, pe, jj * 4 + kh);
            const __half2* hp = reinterpret_cast<const __half2*>(
                g_h16 + (size_t)sj * HC + lane * 4);
            __half2 h01 = __ldg(hp + 0);
            __half2 h23 = __ldg(hp + 1);
            float2 f01 = __half22float2(h01);
            float2 f23 = __half22float2(h23);
            acc.x = fmaf(q, f01.x, acc.x);
            acc.y = fmaf(q, f01.y, acc.y);
            acc.z = fmaf(q, f23.x, acc.z);
            acc.w = fmaf(q, f23.y, acc.w);
        }
    }

    // reduce dnm over the 8 edge slots; lane l then holds denom for head (l&3)
    dnm += __shfl_xor_sync(0xFFFFFFFFu, dnm, 4);
    dnm += __shfl_xor_sync(0xFFFFFFFFu, dnm, 8);
    dnm += __shfl_xor_sync(0xFFFFFFFFu, dnm, 16);
    float dn = __shfl_sync(0xFFFFFFFFu, dnm, kh);
    float inv = 1.f / dn;

    float4 bb = *reinterpret_cast<const float4*>(bias + lane * 4);
    float4 r;
    r.x = acc.x * inv + bb.x;
    r.y = acc.y * inv + bb.y;
    r.z = acc.z * inv + bb.z;
    r.w = acc.w * inv + bb.w;
    r.x = (r.x > 0.f) ? r.x : (__expf(r.x) - 1.f);
    r.y = (r.y > 0.f) ? r.y : (__expf(r.y) - 1.f);
    r.z = (r.z > 0.f) ? r.z : (__expf(r.z) - 1.f);
    r.w = (r.w > 0.f) ? r.w : (__expf(r.w) - 1.f);
    *reinterpret_cast<float4*>(g_z + (size_t)w * HC + lane * 4) = r;
}

// ---------------- GEMM2: out = z @ lin_W + lin_b  (50000x128 * 128x64) -------
// BM=64, BN=64, BK=32, 256 threads; M-paired FFMA2.
__global__ void gemm2_kernel(const float* __restrict__ linW,
                             const float* __restrict__ linb,
                             float* __restrict__ out)
{
    __shared__ float As[32][64];    // [k][m]
    __shared__ float Bs[32][64];    // [k][n]
    const int tid = threadIdx.x;
    const int tx = tid & 15;        // cols tx*4 .. tx*4+3
    const int ty = tid >> 4;        // rows ty*4 .. ty*4+3
    const int bm = blockIdx.x * 64;

    // acc2[ip][j]: row-pair (ty*4+2ip, +1), col tx*4+j
    unsigned long long acc2[2][4];
#pragma unroll
    for (int i = 0; i < 2; ++i)
#pragma unroll
        for (int jx = 0; jx < 4; ++jx) acc2[i][jx] = 0ull;

    for (int k0 = 0; k0 < HC; k0 += 32) {
#pragma unroll
        for (int r = 0; r < 2; ++r) {
            int idx = tid + r * 256;
            int row = idx >> 3;
            int kk4 = idx & 7;
            int gm = bm + row;
            float4 v = make_float4(0.f, 0.f, 0.f, 0.f);
            if (gm < NN)
                v = *reinterpret_cast<const float4*>(g_z + (size_t)gm * HC + k0 + kk4 * 4);
            As[kk4 * 4 + 0][row] = v.x;
            As[kk4 * 4 + 1][row] = v.y;
            As[kk4 * 4 + 2][row] = v.z;
            As[kk4 * 4 + 3][row] = v.w;
        }
#pragma unroll
        for (int r = 0; r < 2; ++r) {
            int idx = tid + r * 256;
            int kk = idx >> 4;
            int nn4 = idx & 15;
            *reinterpret_cast<float4*>(&Bs[kk][nn4 * 4]) =
                *reinterpret_cast<const float4*>(linW + (size_t)(k0 + kk) * OUT_DIM + nn4 * 4);
        }
        __syncthreads();
#pragma unroll
        for (int k = 0; k < 32; ++k) {
            unsigned long long ap[2];
#pragma unroll
            for (int ip = 0; ip < 2; ++ip)
                ap[ip] = *reinterpret_cast<const unsigned long long*>(&As[k][ty * 4 + 2 * ip]);
            float4 bv = reinterpret_cast<const float4*>(&Bs[k][0])[tx];
            unsigned long long bd[4];
            bd[0] = pack2(bv.x, bv.x);
            bd[1] = pack2(bv.y, bv.y);
            bd[2] = pack2(bv.z, bv.z);
            bd[3] = pack2(bv.w, bv.w);
#pragma unroll
            for (int ip = 0; ip < 2; ++ip)
#pragma unroll
                for (int jx = 0; jx < 4; ++jx)
                    acc2[ip][jx] = ffma2(ap[ip], bd[jx], acc2[ip][jx]);
        }
        __syncthreads();
    }
    float4 bb = *reinterpret_cast<const float4*>(linb + tx * 4);
#pragma unroll
    for (int ip = 0; ip < 2; ++ip) {
        float lo0, hi0, lo1, hi1, lo2, hi2, lo3, hi3;
        unpack2(acc2[ip][0], lo0, hi0);
        unpack2(acc2[ip][1], lo1, hi1);
        unpack2(acc2[ip][2], lo2, hi2);
        unpack2(acc2[ip][3], lo3, hi3);
        int gm0 = bm + ty * 4 + 2 * ip;
        int gm1 = gm0 + 1;
        if (gm0 < NN) {
            *reinterpret_cast<float4*>(out + (size_t)gm0 * OUT_DIM + tx * 4) =
                make_float4(lo0 + bb.x, lo1 + bb.y, lo2 + bb.z, lo3 + bb.w);
        }
        if (gm1 < NN) {
            *reinterpret_cast<float4*>(out + (size_t)gm1 * OUT_DIM + tx * 4) =
                make_float4(hi0 + bb.x, hi1 + bb.y, hi2 + bb.z, hi3 + bb.w);
        }
    }
}

// ---------------- launch ------------------------------------------------------
extern "C" void kernel_launch(void* const* d_in, const int* in_sizes, int n_in,
                              void* d_out, int out_size)
{
    const float* x        = (const float*)d_in[0];
    const void*  ei       = (const void*)d_in[1];
    const float* W        = (const float*)d_in[2];
    const float* att_src  = (const float*)d_in[3];
    const float* att_dst  = (const float*)d_in[4];
    const float* bias     = (const float*)d_in[5];
    const float* lin_W    = (const float*)d_in[6];
    const float* lin_b    = (const float*)d_in[7];
    float* out            = (float*)d_out;

    const int warp_blocks = (NN * 32 + 255) / 256;   // 6250
    const int edge_blocks = (EE + 255) / 256;        // 6250
    const int gemm_blocks = (NN + 63) / 64;          // 782

    void* cnt_ptr = nullptr;
    cudaGetSymbolAddress(&cnt_ptr, g_cnt);

    cudaMemsetAsync(cnt_ptr, 0, NN * sizeof(int));                 // launch 0
    fused1_kernel<<<G1BLK + HISTBLK, 256>>>(x, W, ei);             // launch 1
    fused2_kernel<<<SCAN_NBLK + ATTNBLK, 1024>>>(att_src, att_dst);// launch 2
    scan3_kernel<<<SCAN_NBLK, 1024>>>();                           // launch 3
    scatter_kernel<<<edge_blocks, 256>>>(ei);                      // launch 4
    agg_kernel<<<warp_blocks, 256>>>(bias);                        // launch 5
    gemm2_kernel<<<gemm_blocks, 256>>>(lin_W, lin_b, out);         // launch 6
}

// round 11
// speedup vs baseline: 1.5046x; 1.5046x over previous
#include <cuda_runtime.h>
#include <cuda_fp16.h>
#include <cstdint>

// Problem constants (fixed shapes)
#define NN 50000
#define EE 1600000
#define IN_DIM 256
#define HC 128          // H*C = 4*32
#define OUT_DIM 64
#define NEG_SLOPE 0.2f
#define SCAN_NBLK 49    // ceil(50000/1024)
#define G1BLK 782       // gemm1 blocks  (ceil(50000/64))
#define HISTBLK 6250    // hist blocks   (EE/256)
#define ATTNBLK 1563    // attn blocks   (ceil(50000/32) nodes @32 warps/blk)

// ---------------- scratch (__device__ globals; no allocation allowed) -------
__device__ float  g_h[(size_t)NN * HC];    // x @ W (fp32)
__device__ __half g_h16[(size_t)NN * HC];  // fp16 shadow for the gather path
__device__ float  g_asrc[NN * 4];
__device__ float  g_adst[NN * 4];
__device__ float  g_z[(size_t)NN * HC];    // elu(agg + bias)
__device__ int    g_cnt[NN];
__device__ int    g_off[NN + 1];
__device__ int    g_bsum[64];
__device__ int    g_srcsorted[EE];

// ---------------- f32x2 packed FMA helpers (sm_103a FFMA2) -------------------
__device__ __forceinline__ unsigned long long pack2(float lo, float hi)
{
    unsigned long long r;
    asm("mov.b64 %0, {%1, %2};" : "=l"(r) : "f"(lo), "f"(hi));
    return r;
}
__device__ __forceinline__ void unpack2(unsigned long long v, float& lo, float& hi)
{
    asm("mov.b64 {%0, %1}, %2;" : "=f"(lo), "=f"(hi) : "l"(v));
}
__device__ __forceinline__ unsigned long long ffma2(unsigned long long a,
                                                    unsigned long long b,
                                                    unsigned long long c)
{
    unsigned long long d;
    asm("fma.rn.f32x2 %0, %1, %2, %3;" : "=l"(d) : "l"(a), "l"(b), "l"(c));
    return d;
}

// ---------------- per-block edge dtype detection ------------------------------
// int64 little-endian values < 2^31: odd int32 words are all zero.
__device__ __forceinline__ int block_detect_is64(const int* __restrict__ ei32)
{
    int any = 0;
    if (threadIdx.x < 64) any = ei32[2 * threadIdx.x + 1];
    return __syncthreads_or(any) ? 0 : 1;
}

__device__ __forceinline__ int load_edge(const void* ei, size_t idx, int is64)
{
    if (is64) return (int)((const long long*)ei)[idx];
    return ((const int*)ei)[idx];
}

// ---------------- fused1: gemm1 tiles  ||  hist -------------------------------
// gemm1: BM=64, BN=128, BK=32, 256 threads, dup-A FFMA2 (R9 known-good form)
__global__ void fused1_kernel(const float* __restrict__ x,
                              const float* __restrict__ W,
                              const void* __restrict__ ei)
{
    if (blockIdx.x >= G1BLK) {
        // ---- hist path ----
        int is64 = block_detect_is64((const int*)ei);
        int e = (blockIdx.x - G1BLK) * 256 + threadIdx.x;
        if (e < EE) {
            int d = load_edge(ei, (size_t)EE + e, is64);
            if ((unsigned)d < NN) atomicAdd(&g_cnt[d], 1);
        }
        return;
    }
    // ---- gemm1 path ----
    __shared__ float As[32][64];    // [k][m]
    __shared__ float Bs[32][128];   // [k][n]
    const int tid = threadIdx.x;
    const int tx = tid & 31;
    const int ty = tid >> 5;
    const int bm = blockIdx.x * 64;

    unsigned long long acc2[8][2];
#pragma unroll
    for (int i = 0; i < 8; ++i) { acc2[i][0] = 0ull; acc2[i][1] = 0ull; }

    for (int k0 = 0; k0 < IN_DIM; k0 += 32) {
#pragma unroll
        for (int r = 0; r < 2; ++r) {
            int idx = tid + r * 256;
            int row = idx >> 3;
            int kk4 = idx & 7;
            int gm = bm + row;
            float4 v = make_float4(0.f, 0.f, 0.f, 0.f);
            if (gm < NN)
                v = *reinterpret_cast<const float4*>(x + (size_t)gm * IN_DIM + k0 + kk4 * 4);
            As[kk4 * 4 + 0][row] = v.x;
            As[kk4 * 4 + 1][row] = v.y;
            As[kk4 * 4 + 2][row] = v.z;
            As[kk4 * 4 + 3][row] = v.w;
        }
#pragma unroll
        for (int r = 0; r < 4; ++r) {
            int idx = tid + r * 256;
            int kk = idx >> 5;
            int nn4 = idx & 31;
            *reinterpret_cast<float4*>(&Bs[kk][nn4 * 4]) =
                *reinterpret_cast<const float4*>(W + (size_t)(k0 + kk) * HC + nn4 * 4);
        }
        __syncthreads();
#pragma unroll
        for (int k = 0; k < 32; ++k) {
            float4 a0 = reinterpret_cast<const float4*>(&As[k][0])[ty * 2 + 0];
            float4 a1 = reinterpret_cast<const float4*>(&As[k][0])[ty * 2 + 1];
            float4 bv = reinterpret_cast<const float4*>(&Bs[k][0])[tx];
            unsigned long long b01 = pack2(bv.x, bv.y);
            unsigned long long b23 = pack2(bv.z, bv.w);
            float a[8] = {a0.x, a0.y, a0.z, a0.w, a1.x, a1.y, a1.z, a1.w};
#pragma unroll
            for (int i = 0; i < 8; ++i) {
                unsigned long long ai = pack2(a[i], a[i]);
                acc2[i][0] = ffma2(ai, b01, acc2[i][0]);
                acc2[i][1] = ffma2(ai, b23, acc2[i][1]);
            }
        }
        __syncthreads();
    }
#pragma unroll
    for (int i = 0; i < 8; ++i) {
        int gm = bm + ty * 8 + i;
        if (gm < NN) {
            float4 o;
            unpack2(acc2[i][0], o.x, o.y);
            unpack2(acc2[i][1], o.z, o.w);
            *reinterpret_cast<float4*>(g_h + (size_t)gm * HC + tx * 4) = o;
            // fp16 shadow for the gather path
            __half2 h01 = __floats2half2_rn(o.x, o.y);
            __half2 h23 = __floats2half2_rn(o.z, o.w);
            *reinterpret_cast<__half2*>(g_h16 + (size_t)gm * HC + tx * 4 + 0) = h01;
            *reinterpret_cast<__half2*>(g_h16 + (size_t)gm * HC + tx * 4 + 2) = h23;
        }
    }
}

// ---------------- fused2: scan1 (warp-shuffle)  ||  attn_halves ---------------
__global__ void fused2_kernel(const float* __restrict__ att_src,
                              const float* __restrict__ att_dst)
{
    if (blockIdx.x < SCAN_NBLK) {
        __shared__ int wsum[32];
        int t = threadIdx.x;
        int lane = t & 31;
        int wid = t >> 5;
        int i = blockIdx.x * 1024 + t;
        int v = (i < NN) ? g_cnt[i] : 0;
        int sc = v;
#pragma unroll
        for (int off = 1; off < 32; off <<= 1) {
            int n = __shfl_up_sync(0xFFFFFFFFu, sc, off);
            if (lane >= off) sc += n;
        }
        if (lane == 31) wsum[wid] = sc;
        __syncthreads();
        if (wid == 0) {
            int ws = wsum[lane];
#pragma unroll
            for (int off = 1; off < 32; off <<= 1) {
                int n = __shfl_up_sync(0xFFFFFFFFu, ws, off);
                if (lane >= off) ws += n;
            }
            wsum[lane] = ws;
        }
        __syncthreads();
        int base = (wid > 0) ? wsum[wid - 1] : 0;
        int inc = base + sc;
        if (i < NN) g_off[i + 1] = inc;
        if (t == 1023) g_bsum[blockIdx.x] = inc;
        return;
    }
    // ---- attn path ----
    int w = (blockIdx.x - SCAN_NBLK) * 32 + (threadIdx.x >> 5);
    int lane = threadIdx.x & 31;
    if (w >= NN) return;
    float4 hv = *reinterpret_cast<const float4*>(g_h + (size_t)w * HC + lane * 4);
    float4 s4 = *reinterpret_cast<const float4*>(att_src + lane * 4);
    float4 d4 = *reinterpret_cast<const float4*>(att_dst + lane * 4);
    float ps = hv.x * s4.x + hv.y * s4.y + hv.z * s4.z + hv.w * s4.w;
    float pd = hv.x * d4.x + hv.y * d4.y + hv.z * d4.z + hv.w * d4.w;
#pragma unroll
    for (int off = 1; off < 8; off <<= 1) {
        ps += __shfl_xor_sync(0xFFFFFFFFu, ps, off);
        pd += __shfl_xor_sync(0xFFFFFFFFu, pd, off);
    }
    float4 po, qo;
    po.x = __shfl_sync(0xFFFFFFFFu, ps, 0);
    po.y = __shfl_sync(0xFFFFFFFFu, ps, 8);
    po.z = __shfl_sync(0xFFFFFFFFu, ps, 16);
    po.w = __shfl_sync(0xFFFFFFFFu, ps, 24);
    qo.x = __shfl_sync(0xFFFFFFFFu, pd, 0);
    qo.y = __shfl_sync(0xFFFFFFFFu, pd, 8);
    qo.z = __shfl_sync(0xFFFFFFFFu, pd, 16);
    qo.w = __shfl_sync(0xFFFFFFFFu, pd, 24);
    if (lane == 0) {
        *reinterpret_cast<float4*>(g_asrc + w * 4) = po;
        *reinterpret_cast<float4*>(g_adst + w * 4) = qo;
    }
}

// ---------------- scan3: add cross-block prefix -------------------------------
__global__ void scan3_kernel()
{
    __shared__ int s_pref;
    if (threadIdx.x == 0) {
        int acc = 0;
        for (int b = 0; b < (int)blockIdx.x; ++b) acc += g_bsum[b];
        s_pref = acc;
    }
    __syncthreads();
    int i = blockIdx.x * 1024 + threadIdx.x;
    if (i < NN) g_off[i + 1] += s_pref;
    if (i == 0) g_off[0] = 0;
}

// ---------------- scatter: count-down slot assignment -------------------------
__global__ void scatter_kernel(const void* __restrict__ ei)
{
    int is64 = block_detect_is64((const int*)ei);
    int e = blockIdx.x * 256 + threadIdx.x;
    if (e < EE) {
        int d = load_edge(ei, (size_t)EE + e, is64);
        int s = load_edge(ei, (size_t)e, is64);
        if ((unsigned)d < NN && (unsigned)s < NN) {
            int rem = atomicSub(&g_cnt[d], 1);          // old count
            int pos = g_off[d] + rem - 1;
            if ((unsigned)pos < EE) g_srcsorted[pos] = s;
        }
    }
}

// ---------------- aggregation: warp per dst node, software-pipelined ----------
// (single experimental change vs R9; GEMMs reverted)
// Softmax without max-shift (logits bounded, shift-invariant => exact).
// Logit role:     lane = j*4 + kl  (j = edge slot 0..7, kl = head)
// Accumulate role: lane owns channels lane*4..lane*4+3, head kh = lane>>3
__global__ void agg_kernel(const float* __restrict__ bias)
{
    int w = (blockIdx.x * blockDim.x + threadIdx.x) >> 5;
    int lane = threadIdx.x & 31;
    if (w >= NN) return;
    const int kl = lane & 3;
    const int j  = lane >> 2;
    const int kh = lane >> 3;

    float adv_l = g_adst[w * 4 + kl];
    float asl_l = g_asrc[w * 4 + kl];
    float adv_a = g_adst[w * 4 + kh];
    float asl_a = g_asrc[w * 4 + kh];

    // self-loop contribution (fp32 h)
    float e0l = asl_l + adv_l;
    e0l = (e0l > 0.f) ? e0l : NEG_SLOPE * e0l;
    float dnm = (j == 0) ? __expf(e0l) : 0.f;

    float e0a = asl_a + adv_a;
    e0a = (e0a > 0.f) ? e0a : NEG_SLOPE * e0a;
    float pe0a = __expf(e0a);
    float4 hw = *reinterpret_cast<const float4*>(g_h + (size_t)w * HC + lane * 4);
    float4 acc;
    acc.x = pe0a * hw.x; acc.y = pe0a * hw.y;
    acc.z = pe0a * hw.z; acc.w = pe0a * hw.w;

    const int beg = g_off[w];
    const int end = g_off[w + 1];
    int p = beg;

    // software pipeline: prefetch next block's src index + attention half
    int   s_cur = 0;
    float as_cur = 0.f;
    if (p + 8 <= end) {
        s_cur  = g_srcsorted[p + j];
        as_cur = __ldg(g_asrc + (size_t)s_cur * 4 + kl);
    }
    while (p + 8 <= end) {
        const int p_next = p + 8;
        int   s_next = 0;
        float as_next = 0.f;
        if (p_next + 8 <= end) {
            s_next  = g_srcsorted[p_next + j];
            as_next = __ldg(g_asrc + (size_t)s_next * 4 + kl);
        }
        float e = as_cur + adv_l;
        e = (e > 0.f) ? e : NEG_SLOPE * e;
        float pe = __expf(e);
        dnm += pe;
#pragma unroll
        for (int jj = 0; jj < 8; ++jj) {
            int   sj = __shfl_sync(0xFFFFFFFFu, s_cur, jj * 4);
            float q  = __shfl_sync(0xFFFFFFFFu, pe,    jj * 4 + kh);
            const __half2* hp = reinterpret_cast<const __half2*>(
                g_h16 + (size_t)sj * HC + lane * 4);
            __half2 h01 = __ldg(hp + 0);
            __half2 h23 = __ldg(hp + 1);
            float2 f01 = __half22float2(h01);
            float2 f23 = __half22float2(h23);
            acc.x = fmaf(q, f01.x, acc.x);
            acc.y = fmaf(q, f01.y, acc.y);
            acc.z = fmaf(q, f23.x, acc.z);
            acc.w = fmaf(q, f23.y, acc.w);
        }
        s_cur = s_next;
        as_cur = as_next;
        p = p_next;
    }
    if (p < end) {
        int cnt = end - p;
        int ridx = p + ((j < cnt) ? j : (cnt - 1));
        int s = g_srcsorted[ridx];
        float as = __ldg(g_asrc + (size_t)s * 4 + kl);
        float e = as + adv_l;
        e = (e > 0.f) ? e : NEG_SLOPE * e;
        float pe = (j < cnt) ? __expf(e) : 0.f;
        dnm += pe;
        for (int jj = 0; jj < cnt; ++jj) {
            int   sj = __shfl_sync(0xFFFFFFFFu, s,  jj * 4);
            float q  = __shfl_sync(0xFFFFFFFFu, pe, jj * 4 + kh);
            const __half2* hp = reinterpret_cast<const __half2*>(
                g_h16 + (size_t)sj * HC + lane * 4);
            __half2 h01 = __ldg(hp + 0);
            __half2 h23 = __ldg(hp + 1);
            float2 f01 = __half22float2(h01);
            float2 f23 = __half22float2(h23);
            acc.x = fmaf(q, f01.x, acc.x);
            acc.y = fmaf(q, f01.y, acc.y);
            acc.z = fmaf(q, f23.x, acc.z);
            acc.w = fmaf(q, f23.y, acc.w);
        }
    }

    // reduce dnm over the 8 edge slots; lane l then holds denom for head (l&3)
    dnm += __shfl_xor_sync(0xFFFFFFFFu, dnm, 4);
    dnm += __shfl_xor_sync(0xFFFFFFFFu, dnm, 8);
    dnm += __shfl_xor_sync(0xFFFFFFFFu, dnm, 16);
    float dn = __shfl_sync(0xFFFFFFFFu, dnm, kh);
    float inv = 1.f / dn;

    float4 bb = *reinterpret_cast<const float4*>(bias + lane * 4);
    float4 r;
    r.x = acc.x * inv + bb.x;
    r.y = acc.y * inv + bb.y;
    r.z = acc.z * inv + bb.z;
    r.w = acc.w * inv + bb.w;
    r.x = (r.x > 0.f) ? r.x : (__expf(r.x) - 1.f);
    r.y = (r.y > 0.f) ? r.y : (__expf(r.y) - 1.f);
    r.z = (r.z > 0.f) ? r.z : (__expf(r.z) - 1.f);
    r.w = (r.w > 0.f) ? r.w : (__expf(r.w) - 1.f);
    *reinterpret_cast<float4*>(g_z + (size_t)w * HC + lane * 4) = r;
}

// ---------------- GEMM2: out = z @ lin_W + lin_b  (50000x128 * 128x64) -------
// BM=64, BN=64, BK=32, 256 threads, dup-A FFMA2 (R9 known-good form)
__global__ void gemm2_kernel(const float* __restrict__ linW,
                             const float* __restrict__ linb,
                             float* __restrict__ out)
{
    __shared__ float As[32][64];    // [k][m]
    __shared__ float Bs[32][64];    // [k][n]
    const int tid = threadIdx.x;
    const int tx = tid & 15;
    const int ty = tid >> 4;
    const int bm = blockIdx.x * 64;

    unsigned long long acc2[4][2];
#pragma unroll
    for (int i = 0; i < 4; ++i) { acc2[i][0] = 0ull; acc2[i][1] = 0ull; }

    for (int k0 = 0; k0 < HC; k0 += 32) {
#pragma unroll
        for (int r = 0; r < 2; ++r) {
            int idx = tid + r * 256;
            int row = idx >> 3;
            int kk4 = idx & 7;
            int gm = bm + row;
            float4 v = make_float4(0.f, 0.f, 0.f, 0.f);
            if (gm < NN)
                v = *reinterpret_cast<const float4*>(g_z + (size_t)gm * HC + k0 + kk4 * 4);
            As[kk4 * 4 + 0][row] = v.x;
            As[kk4 * 4 + 1][row] = v.y;
            As[kk4 * 4 + 2][row] = v.z;
            As[kk4 * 4 + 3][row] = v.w;
        }
#pragma unroll
        for (int r = 0; r < 2; ++r) {
            int idx = tid + r * 256;
            int kk = idx >> 4;
            int nn4 = idx & 15;
            *reinterpret_cast<float4*>(&Bs[kk][nn4 * 4]) =
                *reinterpret_cast<const float4*>(linW + (size_t)(k0 + kk) * OUT_DIM + nn4 * 4);
        }
        __syncthreads();
#pragma unroll
        for (int k = 0; k < 32; ++k) {
            float4 av = reinterpret_cast<const float4*>(&As[k][0])[ty];
            float4 bv = reinterpret_cast<const float4*>(&Bs[k][0])[tx];
            unsigned long long b01 = pack2(bv.x, bv.y);
            unsigned long long b23 = pack2(bv.z, bv.w);
            float a[4] = {av.x, av.y, av.z, av.w};
#pragma unroll
            for (int i = 0; i < 4; ++i) {
                unsigned long long ai = pack2(a[i], a[i]);
                acc2[i][0] = ffma2(ai, b01, acc2[i][0]);
                acc2[i][1] = ffma2(ai, b23, acc2[i][1]);
            }
        }
        __syncthreads();
    }
    float4 bb = *reinterpret_cast<const float4*>(linb + tx * 4);
#pragma unroll
    for (int i = 0; i < 4; ++i) {
        int gm = bm + ty * 4 + i;
        if (gm < NN) {
            float4 o;
            unpack2(acc2[i][0], o.x, o.y);
            unpack2(acc2[i][1], o.z, o.w);
            o.x += bb.x; o.y += bb.y; o.z += bb.z; o.w += bb.w;
            *reinterpret_cast<float4*>(out + (size_t)gm * OUT_DIM + tx * 4) = o;
        }
    }
}

// ---------------- launch ------------------------------------------------------
extern "C" void kernel_launch(void* const* d_in, const int* in_sizes, int n_in,
                              void* d_out, int out_size)
{
    const float* x        = (const float*)d_in[0];
    const void*  ei       = (const void*)d_in[1];
    const float* W        = (const float*)d_in[2];
    const float* att_src  = (const float*)d_in[3];
    const float* att_dst  = (const float*)d_in[4];
    const float* bias     = (const float*)d_in[5];
    const float* lin_W    = (const float*)d_in[6];
    const float* lin_b    = (const float*)d_in[7];
    float* out            = (float*)d_out;

    const int warp_blocks = (NN * 32 + 255) / 256;   // 6250
    const int edge_blocks = (EE + 255) / 256;        // 6250
    const int gemm_blocks = (NN + 63) / 64;          // 782

    void* cnt_ptr = nullptr;
    cudaGetSymbolAddress(&cnt_ptr, g_cnt);

    cudaMemsetAsync(cnt_ptr, 0, NN * sizeof(int));                 // launch 0
    fused1_kernel<<<G1BLK + HISTBLK, 256>>>(x, W, ei);             // launch 1
    fused2_kernel<<<SCAN_NBLK + ATTNBLK, 1024>>>(att_src, att_dst);// launch 2
    scan3_kernel<<<SCAN_NBLK, 1024>>>();                           // launch 3
    scatter_kernel<<<edge_blocks, 256>>>(ei);                      // launch 4
    agg_kernel<<<warp_blocks, 256>>>(bias);                        // launch 5
    gemm2_kernel<<<gemm_blocks, 256>>>(lin_W, lin_b, out);         // launch 6
}

// round 13
// speedup vs baseline: 1.6287x; 1.0825x over previous
#include <cuda_runtime.h>
#include <cuda_fp16.h>
#include <cstdint>

// Problem constants (fixed shapes)
#define NN 50000
#define EE 1600000
#define IN_DIM 256
#define HC 128          // H*C = 4*32
#define OUT_DIM 64
#define NEG_SLOPE 0.2f
#define SCAN_NBLK 49    // ceil(50000/1024)
#define G1BLK 782       // gemm1 blocks  (ceil(50000/64))
#define HISTBLK 6250    // hist blocks   (EE/256)
#define ATTNBLK 1563    // attn blocks   (ceil(50000/32) nodes @32 warps/blk)

// ---------------- scratch (__device__ globals; no allocation allowed) -------
__device__ float  g_h[(size_t)NN * HC];    // x @ W (fp32)
__device__ __half g_h16[(size_t)NN * HC];  // fp16 shadow for the gather path
__device__ float  g_asrc[NN * 4];
__device__ float  g_adst[NN * 4];
__device__ float  g_z[(size_t)NN * HC];    // elu(agg + bias)
__device__ int    g_cnt[NN];
__device__ int    g_off[NN + 1];
__device__ int    g_bsum[64];
__device__ int    g_srcsorted[EE];

// ---------------- f32x2 packed FMA helpers (sm_103a FFMA2) -------------------
__device__ __forceinline__ unsigned long long pack2(float lo, float hi)
{
    unsigned long long r;
    asm("mov.b64 %0, {%1, %2};" : "=l"(r) : "f"(lo), "f"(hi));
    return r;
}
__device__ __forceinline__ void unpack2(unsigned long long v, float& lo, float& hi)
{
    asm("mov.b64 {%0, %1}, %2;" : "=f"(lo), "=f"(hi) : "l"(v));
}
__device__ __forceinline__ unsigned long long ffma2(unsigned long long a,
                                                    unsigned long long b,
                                                    unsigned long long c)
{
    unsigned long long d;
    asm("fma.rn.f32x2 %0, %1, %2, %3;" : "=l"(d) : "l"(a), "l"(b), "l"(c));
    return d;
}

// ---------------- per-block edge dtype detection ------------------------------
// int64 little-endian values < 2^31: odd int32 words are all zero.
__device__ __forceinline__ int block_detect_is64(const int* __restrict__ ei32)
{
    int any = 0;
    if (threadIdx.x < 64) any = ei32[2 * threadIdx.x + 1];
    return __syncthreads_or(any) ? 0 : 1;
}

__device__ __forceinline__ int load_edge(const void* ei, size_t idx, int is64)
{
    if (is64) return (int)((const long long*)ei)[idx];
    return ((const int*)ei)[idx];
}

// ---------------- fused1: gemm1 tiles  ||  hist -------------------------------
// gemm1: BM=64, BN=128, BK=32, 256 threads, dup-A FFMA2 (known-good form)
__global__ void fused1_kernel(const float* __restrict__ x,
                              const float* __restrict__ W,
                              const void* __restrict__ ei)
{
    if (blockIdx.x >= G1BLK) {
        // ---- hist path ----
        int is64 = block_detect_is64((const int*)ei);
        int e = (blockIdx.x - G1BLK) * 256 + threadIdx.x;
        if (e < EE) {
            int d = load_edge(ei, (size_t)EE + e, is64);
            if ((unsigned)d < NN) atomicAdd(&g_cnt[d], 1);
        }
        return;
    }
    // ---- gemm1 path ----
    __shared__ float As[32][64];    // [k][m]
    __shared__ float Bs[32][128];   // [k][n]
    const int tid = threadIdx.x;
    const int tx = tid & 31;
    const int ty = tid >> 5;
    const int bm = blockIdx.x * 64;

    unsigned long long acc2[8][2];
#pragma unroll
    for (int i = 0; i < 8; ++i) { acc2[i][0] = 0ull; acc2[i][1] = 0ull; }

    for (int k0 = 0; k0 < IN_DIM; k0 += 32) {
#pragma unroll
        for (int r = 0; r < 2; ++r) {
            int idx = tid + r * 256;
            int row = idx >> 3;
            int kk4 = idx & 7;
            int gm = bm + row;
            float4 v = make_float4(0.f, 0.f, 0.f, 0.f);
            if (gm < NN)
                v = *reinterpret_cast<const float4*>(x + (size_t)gm * IN_DIM + k0 + kk4 * 4);
            As[kk4 * 4 + 0][row] = v.x;
            As[kk4 * 4 + 1][row] = v.y;
            As[kk4 * 4 + 2][row] = v.z;
            As[kk4 * 4 + 3][row] = v.w;
        }
#pragma unroll
        for (int r = 0; r < 4; ++r) {
            int idx = tid + r * 256;
            int kk = idx >> 5;
            int nn4 = idx & 31;
            *reinterpret_cast<float4*>(&Bs[kk][nn4 * 4]) =
                *reinterpret_cast<const float4*>(W + (size_t)(k0 + kk) * HC + nn4 * 4);
        }
        __syncthreads();
#pragma unroll
        for (int k = 0; k < 32; ++k) {
            float4 a0 = reinterpret_cast<const float4*>(&As[k][0])[ty * 2 + 0];
            float4 a1 = reinterpret_cast<const float4*>(&As[k][0])[ty * 2 + 1];
            float4 bv = reinterpret_cast<const float4*>(&Bs[k][0])[tx];
            unsigned long long b01 = pack2(bv.x, bv.y);
            unsigned long long b23 = pack2(bv.z, bv.w);
            float a[8] = {a0.x, a0.y, a0.z, a0.w, a1.x, a1.y, a1.z, a1.w};
#pragma unroll
            for (int i = 0; i < 8; ++i) {
                unsigned long long ai = pack2(a[i], a[i]);
                acc2[i][0] = ffma2(ai, b01, acc2[i][0]);
                acc2[i][1] = ffma2(ai, b23, acc2[i][1]);
            }
        }
        __syncthreads();
    }
#pragma unroll
    for (int i = 0; i < 8; ++i) {
        int gm = bm + ty * 8 + i;
        if (gm < NN) {
            float4 o;
            unpack2(acc2[i][0], o.x, o.y);
            unpack2(acc2[i][1], o.z, o.w);
            *reinterpret_cast<float4*>(g_h + (size_t)gm * HC + tx * 4) = o;
            // fp16 shadow for the gather path
            __half2 h01 = __floats2half2_rn(o.x, o.y);
            __half2 h23 = __floats2half2_rn(o.z, o.w);
            *reinterpret_cast<__half2*>(g_h16 + (size_t)gm * HC + tx * 4 + 0) = h01;
            *reinterpret_cast<__half2*>(g_h16 + (size_t)gm * HC + tx * 4 + 2) = h23;
        }
    }
}

// ---------------- fused2: scan1 (warp-shuffle)  ||  attn_halves ---------------
__global__ void fused2_kernel(const float* __restrict__ att_src,
                              const float* __restrict__ att_dst)
{
    if (blockIdx.x < SCAN_NBLK) {
        __shared__ int wsum[32];
        int t = threadIdx.x;
        int lane = t & 31;
        int wid = t >> 5;
        int i = blockIdx.x * 1024 + t;
        int v = (i < NN) ? g_cnt[i] : 0;
        int sc = v;
#pragma unroll
        for (int off = 1; off < 32; off <<= 1) {
            int n = __shfl_up_sync(0xFFFFFFFFu, sc, off);
            if (lane >= off) sc += n;
        }
        if (lane == 31) wsum[wid] = sc;
        __syncthreads();
        if (wid == 0) {
            int ws = wsum[lane];
#pragma unroll
            for (int off = 1; off < 32; off <<= 1) {
                int n = __shfl_up_sync(0xFFFFFFFFu, ws, off);
                if (lane >= off) ws += n;
            }
            wsum[lane] = ws;
        }
        __syncthreads();
        int base = (wid > 0) ? wsum[wid - 1] : 0;
        int inc = base + sc;
        if (i < NN) g_off[i + 1] = inc;
        if (t == 1023) g_bsum[blockIdx.x] = inc;
        return;
    }
    // ---- attn path ----
    int w = (blockIdx.x - SCAN_NBLK) * 32 + (threadIdx.x >> 5);
    int lane = threadIdx.x & 31;
    if (w >= NN) return;
    float4 hv = *reinterpret_cast<const float4*>(g_h + (size_t)w * HC + lane * 4);
    float4 s4 = *reinterpret_cast<const float4*>(att_src + lane * 4);
    float4 d4 = *reinterpret_cast<const float4*>(att_dst + lane * 4);
    float ps = hv.x * s4.x + hv.y * s4.y + hv.z * s4.z + hv.w * s4.w;
    float pd = hv.x * d4.x + hv.y * d4.y + hv.z * d4.z + hv.w * d4.w;
#pragma unroll
    for (int off = 1; off < 8; off <<= 1) {
        ps += __shfl_xor_sync(0xFFFFFFFFu, ps, off);
        pd += __shfl_xor_sync(0xFFFFFFFFu, pd, off);
    }
    float4 po, qo;
    po.x = __shfl_sync(0xFFFFFFFFu, ps, 0);
    po.y = __shfl_sync(0xFFFFFFFFu, ps, 8);
    po.z = __shfl_sync(0xFFFFFFFFu, ps, 16);
    po.w = __shfl_sync(0xFFFFFFFFu, ps, 24);
    qo.x = __shfl_sync(0xFFFFFFFFu, pd, 0);
    qo.y = __shfl_sync(0xFFFFFFFFu, pd, 8);
    qo.z = __shfl_sync(0xFFFFFFFFu, pd, 16);
    qo.w = __shfl_sync(0xFFFFFFFFu, pd, 24);
    if (lane == 0) {
        *reinterpret_cast<float4*>(g_asrc + w * 4) = po;
        *reinterpret_cast<float4*>(g_adst + w * 4) = qo;
    }
}

// ---------------- scan3: add cross-block prefix -------------------------------
__global__ void scan3_kernel()
{
    __shared__ int s_pref;
    if (threadIdx.x == 0) {
        int acc = 0;
        for (int b = 0; b < (int)blockIdx.x; ++b) acc += g_bsum[b];
        s_pref = acc;
    }
    __syncthreads();
    int i = blockIdx.x * 1024 + threadIdx.x;
    if (i < NN) g_off[i + 1] += s_pref;
    if (i == 0) g_off[0] = 0;
}

// ---------------- scatter: count-down slot assignment -------------------------
__global__ void scatter_kernel(const void* __restrict__ ei)
{
    int is64 = block_detect_is64((const int*)ei);
    int e = blockIdx.x * 256 + threadIdx.x;
    if (e < EE) {
        int d = load_edge(ei, (size_t)EE + e, is64);
        int s = load_edge(ei, (size_t)e, is64);
        if ((unsigned)d < NN && (unsigned)s < NN) {
            int rem = atomicSub(&g_cnt[d], 1);          // old count
            int pos = g_off[d] + rem - 1;
            if ((unsigned)pos < EE) g_srcsorted[pos] = s;
        }
    }
}

// ---------------- aggregation: warp per dst node (R9 structure) --------------
// Single change vs R9: the 8-edge inner loop is split into shfl-batch /
// gather-batch / fma-batch phases to front-batch the 8 LDG.64 gathers (MLP=8).
// Softmax without max-shift (logits bounded, shift-invariant => exact).
// Logit role:     lane = j*4 + kl  (j = edge slot 0..7, kl = head)
// Accumulate role: lane owns channels lane*4..lane*4+3, head kh = lane>>3
__global__ void __launch_bounds__(256) agg_kernel(const float* __restrict__ bias)
{
    int w = (blockIdx.x * blockDim.x + threadIdx.x) >> 5;
    int lane = threadIdx.x & 31;
    if (w >= NN) return;
    const int kl = lane & 3;
    const int j  = lane >> 2;
    const int kh = lane >> 3;

    float adv_l = g_adst[w * 4 + kl];
    float asl_l = g_asrc[w * 4 + kl];
    float adv_a = g_adst[w * 4 + kh];
    float asl_a = g_asrc[w * 4 + kh];

    // self-loop contribution (fp32 h)
    float e0l = asl_l + adv_l;
    e0l = (e0l > 0.f) ? e0l : NEG_SLOPE * e0l;
    float dnm = (j == 0) ? __expf(e0l) : 0.f;

    float e0a = asl_a + adv_a;
    e0a = (e0a > 0.f) ? e0a : NEG_SLOPE * e0a;
    float pe0a = __expf(e0a);
    float4 hw = *reinterpret_cast<const float4*>(g_h + (size_t)w * HC + lane * 4);
    float4 acc;
    acc.x = pe0a * hw.x; acc.y = pe0a * hw.y;
    acc.z = pe0a * hw.z; acc.w = pe0a * hw.w;

    const int beg = g_off[w];
    const int end = g_off[w + 1];
    int p = beg;
    for (; p + 8 <= end; p += 8) {
        int s = g_srcsorted[p + j];
        float as = __ldg(g_asrc + (size_t)s * 4 + kl);
        float e = as + adv_l;
        e = (e > 0.f) ? e : NEG_SLOPE * e;
        float pe = __expf(e);
        dnm += pe;
        // phase 1: broadcast indices + weights
        int   sj[8];
        float q[8];
#pragma unroll
        for (int jj = 0; jj < 8; ++jj) {
            sj[jj] = __shfl_sync(0xFFFFFFFFu, s,  jj * 4);
            q[jj]  = __shfl_sync(0xFFFFFFFFu, pe, jj * 4 + kh);
        }
        // phase 2: issue all 8 gathers back-to-back (MLP=8)
        __half2 h01[8], h23[8];
#pragma unroll
        for (int jj = 0; jj < 8; ++jj) {
            const __half2* hp = reinterpret_cast<const __half2*>(
                g_h16 + (size_t)sj[jj] * HC + lane * 4);
            h01[jj] = __ldg(hp + 0);
            h23[jj] = __ldg(hp + 1);
        }
        // phase 3: accumulate
#pragma unroll
        for (int jj = 0; jj < 8; ++jj) {
            float2 f01 = __half22float2(h01[jj]);
            float2 f23 = __half22float2(h23[jj]);
            acc.x = fmaf(q[jj], f01.x, acc.x);
            acc.y = fmaf(q[jj], f01.y, acc.y);
            acc.z = fmaf(q[jj], f23.x, acc.z);
            acc.w = fmaf(q[jj], f23.y, acc.w);
        }
    }
    if (p < end) {
        int cnt = end - p;
        int ridx = p + ((j < cnt) ? j : (cnt - 1));
        int s = g_srcsorted[ridx];
        float as = __ldg(g_asrc + (size_t)s * 4 + kl);
        float e = as + adv_l;
        e = (e > 0.f) ? e : NEG_SLOPE * e;
        float pe = (j < cnt) ? __expf(e) : 0.f;
        dnm += pe;
        for (int jj = 0; jj < cnt; ++jj) {
            int   sj = __shfl_sync(0xFFFFFFFFu, s,  jj * 4);
            float qv = __shfl_sync(0xFFFFFFFFu, pe, jj * 4 + kh);
            const __half2* hp = reinterpret_cast<const __half2*>(
                g_h16 + (size_t)sj * HC + lane * 4);
            __half2 a01 = __ldg(hp + 0);
            __half2 a23 = __ldg(hp + 1);
            float2 f01 = __half22float2(a01);
            float2 f23 = __half22float2(a23);
            acc.x = fmaf(qv, f01.x, acc.x);
            acc.y = fmaf(qv, f01.y, acc.y);
            acc.z = fmaf(qv, f23.x, acc.z);
            acc.w = fmaf(qv, f23.y, acc.w);
        }
    }

    // reduce dnm over the 8 edge slots; lane l then holds denom for head (l&3)
    dnm += __shfl_xor_sync(0xFFFFFFFFu, dnm, 4);
    dnm += __shfl_xor_sync(0xFFFFFFFFu, dnm, 8);
    dnm += __shfl_xor_sync(0xFFFFFFFFu, dnm, 16);
    float dn = __shfl_sync(0xFFFFFFFFu, dnm, kh);
    float inv = 1.f / dn;

    float4 bb = *reinterpret_cast<const float4*>(bias + lane * 4);
    float4 r;
    r.x = acc.x * inv + bb.x;
    r.y = acc.y * inv + bb.y;
    r.z = acc.z * inv + bb.z;
    r.w = acc.w * inv + bb.w;
    r.x = (r.x > 0.f) ? r.x : (__expf(r.x) - 1.f);
    r.y = (r.y > 0.f) ? r.y : (__expf(r.y) - 1.f);
    r.z = (r.z > 0.f) ? r.z : (__expf(r.z) - 1.f);
    r.w = (r.w > 0.f) ? r.w : (__expf(r.w) - 1.f);
    *reinterpret_cast<float4*>(g_z + (size_t)w * HC + lane * 4) = r;
}

// ---------------- GEMM2: out = z @ lin_W + lin_b  (50000x128 * 128x64) -------
// BM=64, BN=64, BK=32, 256 threads, dup-A FFMA2 (known-good form)
__global__ void gemm2_kernel(const float* __restrict__ linW,
                             const float* __restrict__ linb,
                             float* __restrict__ out)
{
    __shared__ float As[32][64];    // [k][m]
    __shared__ float Bs[32][64];    // [k][n]
    const int tid = threadIdx.x;
    const int tx = tid & 15;
    const int ty = tid >> 4;
    const int bm = blockIdx.x * 64;

    unsigned long long acc2[4][2];
#pragma unroll
    for (int i = 0; i < 4; ++i) { acc2[i][0] = 0ull; acc2[i][1] = 0ull; }

    for (int k0 = 0; k0 < HC; k0 += 32) {
#pragma unroll
        for (int r = 0; r < 2; ++r) {
            int idx = tid + r * 256;
            int row = idx >> 3;
            int kk4 = idx & 7;
            int gm = bm + row;
            float4 v = make_float4(0.f, 0.f, 0.f, 0.f);
            if (gm < NN)
                v = *reinterpret_cast<const float4*>(g_z + (size_t)gm * HC + k0 + kk4 * 4);
            As[kk4 * 4 + 0][row] = v.x;
            As[kk4 * 4 + 1][row] = v.y;
            As[kk4 * 4 + 2][row] = v.z;
            As[kk4 * 4 + 3][row] = v.w;
        }
#pragma unroll
        for (int r = 0; r < 2; ++r) {
            int idx = tid + r * 256;
            int kk = idx >> 4;
            int nn4 = idx & 15;
            *reinterpret_cast<float4*>(&Bs[kk][nn4 * 4]) =
                *reinterpret_cast<const float4*>(linW + (size_t)(k0 + kk) * OUT_DIM + nn4 * 4);
        }
        __syncthreads();
#pragma unroll
        for (int k = 0; k < 32; ++k) {
            float4 av = reinterpret_cast<const float4*>(&As[k][0])[ty];
            float4 bv = reinterpret_cast<const float4*>(&Bs[k][0])[tx];
            unsigned long long b01 = pack2(bv.x, bv.y);
            unsigned long long b23 = pack2(bv.z, bv.w);
            float a[4] = {av.x, av.y, av.z, av.w};
#pragma unroll
            for (int i = 0; i < 4; ++i) {
                unsigned long long ai = pack2(a[i], a[i]);
                acc2[i][0] = ffma2(ai, b01, acc2[i][0]);
                acc2[i][1] = ffma2(ai, b23, acc2[i][1]);
            }
        }
        __syncthreads();
    }
    float4 bb = *reinterpret_cast<const float4*>(linb + tx * 4);
#pragma unroll
    for (int i = 0; i < 4; ++i) {
        int gm = bm + ty * 4 + i;
        if (gm < NN) {
            float4 o;
            unpack2(acc2[i][0], o.x, o.y);
            unpack2(acc2[i][1], o.z, o.w);
            o.x += bb.x; o.y += bb.y; o.z += bb.z; o.w += bb.w;
            *reinterpret_cast<float4*>(out + (size_t)gm * OUT_DIM + tx * 4) = o;
        }
    }
}

// ---------------- launch ------------------------------------------------------
extern "C" void kernel_launch(void* const* d_in, const int* in_sizes, int n_in,
                              void* d_out, int out_size)
{
    const float* x        = (const float*)d_in[0];
    const void*  ei       = (const void*)d_in[1];
    const float* W        = (const float*)d_in[2];
    const float* att_src  = (const float*)d_in[3];
    const float* att_dst  = (const float*)d_in[4];
    const float* bias     = (const float*)d_in[5];
    const float* lin_W    = (const float*)d_in[6];
    const float* lin_b    = (const float*)d_in[7];
    float* out            = (float*)d_out;

    const int warp_blocks = (NN * 32 + 255) / 256;   // 6250
    const int edge_blocks = (EE + 255) / 256;        // 6250
    const int gemm_blocks = (NN + 63) / 64;          // 782

    void* cnt_ptr = nullptr;
    cudaGetSymbolAddress(&cnt_ptr, g_cnt);

    cudaMemsetAsync(cnt_ptr, 0, NN * sizeof(int));                 // launch 0
    fused1_kernel<<<G1BLK + HISTBLK, 256>>>(x, W, ei);             // launch 1
    fused2_kernel<<<SCAN_NBLK + ATTNBLK, 1024>>>(att_src, att_dst);// launch 2
    scan3_kernel<<<SCAN_NBLK, 1024>>>();                           // launch 3
    scatter_kernel<<<edge_blocks, 256>>>(ei);                      // launch 4
    agg_kernel<<<warp_blocks, 256>>>(bias);                        // launch 5
    gemm2_kernel<<<gemm_blocks, 256>>>(lin_W, lin_b, out);         // launch 6
}

// round 14
// speedup vs baseline: 1.6478x; 1.0117x over previous
#include <cuda_runtime.h>
#include <cuda_fp16.h>
#include <cstdint>

// Problem constants (fixed shapes)
#define NN 50000
#define EE 1600000
#define IN_DIM 256
#define HC 128          // H*C = 4*32
#define OUT_DIM 64
#define NEG_SLOPE 0.2f
#define SCAN_NBLK 49    // ceil(50000/1024)
#define G1BLK 782       // gemm1 blocks  (ceil(50000/64))
#define HISTBLK 6250    // hist blocks   (EE/256)
#define SCATBLK 6250    // scatter blocks (EE/256)
#define ATTNBLK 6250    // attn blocks   (50000 nodes @8 warps/blk)

// ---------------- scratch (__device__ globals; no allocation allowed) -------
// NOTE: g_cnt is self-restoring: hist does +1 per (valid-d) edge, scatter does
// -1 per (valid-d) edge => returns to all-zero after every full run. No memset.
__device__ float  g_h[(size_t)NN * HC];    // x @ W (fp32)
__device__ __half g_h16[(size_t)NN * HC];  // fp16 shadow for the gather path
__device__ float  g_asrc[NN * 4];
__device__ float  g_adst[NN * 4];
__device__ float  g_z[(size_t)NN * HC];    // elu(agg + bias)
__device__ int    g_cnt[NN];               // zero-init at load; self-restoring
__device__ int    g_off[NN + 1];
__device__ int    g_bsum[64];
__device__ int    g_srcsorted[EE];

// ---------------- f32x2 packed FMA helpers (sm_103a FFMA2) -------------------
__device__ __forceinline__ unsigned long long pack2(float lo, float hi)
{
    unsigned long long r;
    asm("mov.b64 %0, {%1, %2};" : "=l"(r) : "f"(lo), "f"(hi));
    return r;
}
__device__ __forceinline__ void unpack2(unsigned long long v, float& lo, float& hi)
{
    asm("mov.b64 {%0, %1}, %2;" : "=f"(lo), "=f"(hi) : "l"(v));
}
__device__ __forceinline__ unsigned long long ffma2(unsigned long long a,
                                                    unsigned long long b,
                                                    unsigned long long c)
{
    unsigned long long d;
    asm("fma.rn.f32x2 %0, %1, %2, %3;" : "=l"(d) : "l"(a), "l"(b), "l"(c));
    return d;
}

// ---------------- per-block edge dtype detection ------------------------------
// int64 little-endian values < 2^31: odd int32 words are all zero.
__device__ __forceinline__ int block_detect_is64(const int* __restrict__ ei32)
{
    int any = 0;
    if (threadIdx.x < 64) any = ei32[2 * threadIdx.x + 1];
    return __syncthreads_or(any) ? 0 : 1;
}

__device__ __forceinline__ int load_edge(const void* ei, size_t idx, int is64)
{
    if (is64) return (int)((const long long*)ei)[idx];
    return ((const int*)ei)[idx];
}

// ---------------- fused1: gemm1 tiles  ||  hist -------------------------------
// gemm1: BM=64, BN=128, BK=32, 256 threads, dup-A FFMA2 (known-good form)
__global__ void fused1_kernel(const float* __restrict__ x,
                              const float* __restrict__ W,
                              const void* __restrict__ ei)
{
    if (blockIdx.x >= G1BLK) {
        // ---- hist path ----
        int is64 = block_detect_is64((const int*)ei);
        int e = (blockIdx.x - G1BLK) * 256 + threadIdx.x;
        if (e < EE) {
            int d = load_edge(ei, (size_t)EE + e, is64);
            if ((unsigned)d < NN) atomicAdd(&g_cnt[d], 1);
        }
        return;
    }
    // ---- gemm1 path ----
    __shared__ float As[32][64];    // [k][m]
    __shared__ float Bs[32][128];   // [k][n]
    const int tid = threadIdx.x;
    const int tx = tid & 31;
    const int ty = tid >> 5;
    const int bm = blockIdx.x * 64;

    unsigned long long acc2[8][2];
#pragma unroll
    for (int i = 0; i < 8; ++i) { acc2[i][0] = 0ull; acc2[i][1] = 0ull; }

    for (int k0 = 0; k0 < IN_DIM; k0 += 32) {
#pragma unroll
        for (int r = 0; r < 2; ++r) {
            int idx = tid + r * 256;
            int row = idx >> 3;
            int kk4 = idx & 7;
            int gm = bm + row;
            float4 v = make_float4(0.f, 0.f, 0.f, 0.f);
            if (gm < NN)
                v = *reinterpret_cast<const float4*>(x + (size_t)gm * IN_DIM + k0 + kk4 * 4);
            As[kk4 * 4 + 0][row] = v.x;
            As[kk4 * 4 + 1][row] = v.y;
            As[kk4 * 4 + 2][row] = v.z;
            As[kk4 * 4 + 3][row] = v.w;
        }
#pragma unroll
        for (int r = 0; r < 4; ++r) {
            int idx = tid + r * 256;
            int kk = idx >> 5;
            int nn4 = idx & 31;
            *reinterpret_cast<float4*>(&Bs[kk][nn4 * 4]) =
                *reinterpret_cast<const float4*>(W + (size_t)(k0 + kk) * HC + nn4 * 4);
        }
        __syncthreads();
#pragma unroll
        for (int k = 0; k < 32; ++k) {
            float4 a0 = reinterpret_cast<const float4*>(&As[k][0])[ty * 2 + 0];
            float4 a1 = reinterpret_cast<const float4*>(&As[k][0])[ty * 2 + 1];
            float4 bv = reinterpret_cast<const float4*>(&Bs[k][0])[tx];
            unsigned long long b01 = pack2(bv.x, bv.y);
            unsigned long long b23 = pack2(bv.z, bv.w);
            float a[8] = {a0.x, a0.y, a0.z, a0.w, a1.x, a1.y, a1.z, a1.w};
#pragma unroll
            for (int i = 0; i < 8; ++i) {
                unsigned long long ai = pack2(a[i], a[i]);
                acc2[i][0] = ffma2(ai, b01, acc2[i][0]);
                acc2[i][1] = ffma2(ai, b23, acc2[i][1]);
            }
        }
        __syncthreads();
    }
#pragma unroll
    for (int i = 0; i < 8; ++i) {
        int gm = bm + ty * 8 + i;
        if (gm < NN) {
            float4 o;
            unpack2(acc2[i][0], o.x, o.y);
            unpack2(acc2[i][1], o.z, o.w);
            *reinterpret_cast<float4*>(g_h + (size_t)gm * HC + tx * 4) = o;
            // fp16 shadow for the gather path
            __half2 h01 = __floats2half2_rn(o.x, o.y);
            __half2 h23 = __floats2half2_rn(o.z, o.w);
            *reinterpret_cast<__half2*>(g_h16 + (size_t)gm * HC + tx * 4 + 0) = h01;
            *reinterpret_cast<__half2*>(g_h16 + (size_t)gm * HC + tx * 4 + 2) = h23;
        }
    }
}

// ---------------- scan1: per-block inclusive scan of g_cnt --------------------
__global__ void scan1_kernel()
{
    __shared__ int wsum[32];
    int t = threadIdx.x;
    int lane = t & 31;
    int wid = t >> 5;
    int i = blockIdx.x * 1024 + t;
    int v = (i < NN) ? g_cnt[i] : 0;
    int sc = v;
#pragma unroll
    for (int off = 1; off < 32; off <<= 1) {
        int n = __shfl_up_sync(0xFFFFFFFFu, sc, off);
        if (lane >= off) sc += n;
    }
    if (lane == 31) wsum[wid] = sc;
    __syncthreads();
    if (wid == 0) {
        int ws = wsum[lane];
#pragma unroll
        for (int off = 1; off < 32; off <<= 1) {
            int n = __shfl_up_sync(0xFFFFFFFFu, ws, off);
            if (lane >= off) ws += n;
        }
        wsum[lane] = ws;
    }
    __syncthreads();
    int base = (wid > 0) ? wsum[wid - 1] : 0;
    int inc = base + sc;
    if (i < NN) g_off[i + 1] = inc;
    if (t == 1023) g_bsum[blockIdx.x] = inc;
}

// ---------------- scan3: add cross-block prefix -------------------------------
__global__ void scan3_kernel()
{
    __shared__ int s_pref;
    if (threadIdx.x == 0) {
        int acc = 0;
        for (int b = 0; b < (int)blockIdx.x; ++b) acc += g_bsum[b];
        s_pref = acc;
    }
    __syncthreads();
    int i = blockIdx.x * 1024 + threadIdx.x;
    if (i < NN) g_off[i + 1] += s_pref;
    if (i == 0) g_off[0] = 0;
}

// ---------------- fused3: scatter  ||  attn_halves ----------------------------
// blocks [0, SCATBLK)            : scatter edges into CSR (count-down slots)
// blocks [SCATBLK, +ATTNBLK)     : per-node attention halves (8 warps/block)
__global__ void fused3_kernel(const void* __restrict__ ei,
                              const float* __restrict__ att_src,
                              const float* __restrict__ att_dst)
{
    if (blockIdx.x < SCATBLK) {
        // ---- scatter path ----
        int is64 = block_detect_is64((const int*)ei);
        int e = blockIdx.x * 256 + threadIdx.x;
        if (e < EE) {
            int d = load_edge(ei, (size_t)EE + e, is64);
            int s = load_edge(ei, (size_t)e, is64);
            if ((unsigned)d < NN) {                 // decrement matches hist exactly
                int rem = atomicSub(&g_cnt[d], 1);  // old count
                int pos = g_off[d] + rem - 1;
                if ((unsigned)s < NN && (unsigned)pos < EE) g_srcsorted[pos] = s;
            }
        }
        return;
    }
    // ---- attn path ----
    int w = (blockIdx.x - SCATBLK) * 8 + (threadIdx.x >> 5);
    int lane = threadIdx.x & 31;
    if (w >= NN) return;
    float4 hv = *reinterpret_cast<const float4*>(g_h + (size_t)w * HC + lane * 4);
    float4 s4 = *reinterpret_cast<const float4*>(att_src + lane * 4);
    float4 d4 = *reinterpret_cast<const float4*>(att_dst + lane * 4);
    float ps = hv.x * s4.x + hv.y * s4.y + hv.z * s4.z + hv.w * s4.w;
    float pd = hv.x * d4.x + hv.y * d4.y + hv.z * d4.z + hv.w * d4.w;
#pragma unroll
    for (int off = 1; off < 8; off <<= 1) {
        ps += __shfl_xor_sync(0xFFFFFFFFu, ps, off);
        pd += __shfl_xor_sync(0xFFFFFFFFu, pd, off);
    }
    float4 po, qo;
    po.x = __shfl_sync(0xFFFFFFFFu, ps, 0);
    po.y = __shfl_sync(0xFFFFFFFFu, ps, 8);
    po.z = __shfl_sync(0xFFFFFFFFu, ps, 16);
    po.w = __shfl_sync(0xFFFFFFFFu, ps, 24);
    qo.x = __shfl_sync(0xFFFFFFFFu, pd, 0);
    qo.y = __shfl_sync(0xFFFFFFFFu, pd, 8);
    qo.z = __shfl_sync(0xFFFFFFFFu, pd, 16);
    qo.w = __shfl_sync(0xFFFFFFFFu, pd, 24);
    if (lane == 0) {
        *reinterpret_cast<float4*>(g_asrc + w * 4) = po;
        *reinterpret_cast<float4*>(g_adst + w * 4) = qo;
    }
}

// ---------------- aggregation: warp per dst node, 16-edge batches -------------
// Softmax without max-shift (logits bounded, shift-invariant => exact).
// Logit role:     lane = j*4 + kl  (j = edge slot 0..7, kl = head); each lane
//                 covers 2 edges per 16-batch (slots j and j+8).
// Accumulate role: lane owns channels lane*4..lane*4+3, head kh = lane>>3
__global__ void __launch_bounds__(256) agg_kernel(const float* __restrict__ bias)
{
    int w = (blockIdx.x * blockDim.x + threadIdx.x) >> 5;
    int lane = threadIdx.x & 31;
    if (w >= NN) return;
    const int kl = lane & 3;
    const int j  = lane >> 2;
    const int kh = lane >> 3;

    float adv_l = g_adst[w * 4 + kl];
    float asl_l = g_asrc[w * 4 + kl];
    float adv_a = g_adst[w * 4 + kh];
    float asl_a = g_asrc[w * 4 + kh];

    // self-loop contribution (fp32 h)
    float e0l = asl_l + adv_l;
    e0l = (e0l > 0.f) ? e0l : NEG_SLOPE * e0l;
    float dnm = (j == 0) ? __expf(e0l) : 0.f;

    float e0a = asl_a + adv_a;
    e0a = (e0a > 0.f) ? e0a : NEG_SLOPE * e0a;
    float pe0a = __expf(e0a);
    float4 hw = *reinterpret_cast<const float4*>(g_h + (size_t)w * HC + lane * 4);
    float4 acc;
    acc.x = pe0a * hw.x; acc.y = pe0a * hw.y;
    acc.z = pe0a * hw.z; acc.w = pe0a * hw.w;

    const int beg = g_off[w];
    const int end = g_off[w + 1];
    int p = beg;

    // ---- 16-edge blocks: MLP=16 gather burst ----
    for (; p + 16 <= end; p += 16) {
        int s0 = g_srcsorted[p + j];
        int s1 = g_srcsorted[p + 8 + j];
        float as0 = __ldg(g_asrc + (size_t)s0 * 4 + kl);
        float as1 = __ldg(g_asrc + (size_t)s1 * 4 + kl);
        float ea = as0 + adv_l;
        ea = (ea > 0.f) ? ea : NEG_SLOPE * ea;
        float eb = as1 + adv_l;
        eb = (eb > 0.f) ? eb : NEG_SLOPE * eb;
        float pe0 = __expf(ea);
        float pe1 = __expf(eb);
        dnm += pe0 + pe1;
        // phase 1: broadcast indices
        int sj[16];
#pragma unroll
        for (int jj = 0; jj < 8; ++jj) {
            sj[jj]     = __shfl_sync(0xFFFFFFFFu, s0, jj * 4);
            sj[8 + jj] = __shfl_sync(0xFFFFFFFFu, s1, jj * 4);
        }
        // phase 2: issue all 16 gathers back-to-back (MLP=16)
        __half2 h01[16], h23[16];
#pragma unroll
        for (int jj = 0; jj < 16; ++jj) {
            const __half2* hp = reinterpret_cast<const __half2*>(
                g_h16 + (size_t)sj[jj] * HC + lane * 4);
            h01[jj] = __ldg(hp + 0);
            h23[jj] = __ldg(hp + 1);
        }
        // phase 3: weights via shfl + accumulate
#pragma unroll
        for (int jj = 0; jj < 8; ++jj) {
            float q0 = __shfl_sync(0xFFFFFFFFu, pe0, jj * 4 + kh);
            float2 f01 = __half22float2(h01[jj]);
            float2 f23 = __half22float2(h23[jj]);
            acc.x = fmaf(q0, f01.x, acc.x);
            acc.y = fmaf(q0, f01.y, acc.y);
            acc.z = fmaf(q0, f23.x, acc.z);
            acc.w = fmaf(q0, f23.y, acc.w);
        }
#pragma unroll
        for (int jj = 0; jj < 8; ++jj) {
            float q1 = __shfl_sync(0xFFFFFFFFu, pe1, jj * 4 + kh);
            float2 f01 = __half22float2(h01[8 + jj]);
            float2 f23 = __half22float2(h23[8 + jj]);
            acc.x = fmaf(q1, f01.x, acc.x);
            acc.y = fmaf(q1, f01.y, acc.y);
            acc.z = fmaf(q1, f23.x, acc.z);
            acc.w = fmaf(q1, f23.y, acc.w);
        }
    }

    // ---- one 8-edge block (MLP=8) ----
    if (p + 8 <= end) {
        int s = g_srcsorted[p + j];
        float as = __ldg(g_asrc + (size_t)s * 4 + kl);
        float e = as + adv_l;
        e = (e > 0.f) ? e : NEG_SLOPE * e;
        float pe = __expf(e);
        dnm += pe;
        int   sj[8];
        float q[8];
#pragma unroll
        for (int jj = 0; jj < 8; ++jj) {
            sj[jj] = __shfl_sync(0xFFFFFFFFu, s,  jj * 4);
            q[jj]  = __shfl_sync(0xFFFFFFFFu, pe, jj * 4 + kh);
        }
        __half2 h01[8], h23[8];
#pragma unroll
        for (int jj = 0; jj < 8; ++jj) {
            const __half2* hp = reinterpret_cast<const __half2*>(
                g_h16 + (size_t)sj[jj] * HC + lane * 4);
            h01[jj] = __ldg(hp + 0);
            h23[jj] = __ldg(hp + 1);
        }
#pragma unroll
        for (int jj = 0; jj < 8; ++jj) {
            float2 f01 = __half22float2(h01[jj]);
            float2 f23 = __half22float2(h23[jj]);
            acc.x = fmaf(q[jj], f01.x, acc.x);
            acc.y = fmaf(q[jj], f01.y, acc.y);
            acc.z = fmaf(q[jj], f23.x, acc.z);
            acc.w = fmaf(q[jj], f23.y, acc.w);
        }
        p += 8;
    }

    // ---- tail (< 8 edges) ----
    if (p < end) {
        int cnt = end - p;
        int ridx = p + ((j < cnt) ? j : (cnt - 1));
        int s = g_srcsorted[ridx];
        float as = __ldg(g_asrc + (size_t)s * 4 + kl);
        float e = as + adv_l;
        e = (e > 0.f) ? e : NEG_SLOPE * e;
        float pe = (j < cnt) ? __expf(e) : 0.f;
        dnm += pe;
        for (int jj = 0; jj < cnt; ++jj) {
            int   sj = __shfl_sync(0xFFFFFFFFu, s,  jj * 4);
            float qv = __shfl_sync(0xFFFFFFFFu, pe, jj * 4 + kh);
            const __half2* hp = reinterpret_cast<const __half2*>(
                g_h16 + (size_t)sj * HC + lane * 4);
            __half2 a01 = __ldg(hp + 0);
            __half2 a23 = __ldg(hp + 1);
            float2 f01 = __half22float2(a01);
            float2 f23 = __half22float2(a23);
            acc.x = fmaf(qv, f01.x, acc.x);
            acc.y = fmaf(qv, f01.y, acc.y);
            acc.z = fmaf(qv, f23.x, acc.z);
            acc.w = fmaf(qv, f23.y, acc.w);
        }
    }

    // reduce dnm over the 8 edge slots; lane l then holds denom for head (l&3)
    dnm += __shfl_xor_sync(0xFFFFFFFFu, dnm, 4);
    dnm += __shfl_xor_sync(0xFFFFFFFFu, dnm, 8);
    dnm += __shfl_xor_sync(0xFFFFFFFFu, dnm, 16);
    float dn = __shfl_sync(0xFFFFFFFFu, dnm, kh);
    float inv = 1.f / dn;

    float4 bb = *reinterpret_cast<const float4*>(bias + lane * 4);
    float4 r;
    r.x = acc.x * inv + bb.x;
    r.y = acc.y * inv + bb.y;
    r.z = acc.z * inv + bb.z;
    r.w = acc.w * inv + bb.w;
    r.x = (r.x > 0.f) ? r.x : (__expf(r.x) - 1.f);
    r.y = (r.y > 0.f) ? r.y : (__expf(r.y) - 1.f);
    r.z = (r.z > 0.f) ? r.z : (__expf(r.z) - 1.f);
    r.w = (r.w > 0.f) ? r.w : (__expf(r.w) - 1.f);
    *reinterpret_cast<float4*>(g_z + (size_t)w * HC + lane * 4) = r;
}

// ---------------- GEMM2: out = z @ lin_W + lin_b  (50000x128 * 128x64) -------
// BM=64, BN=64, BK=32, 256 threads, dup-A FFMA2 (known-good form)
__global__ void gemm2_kernel(const float* __restrict__ linW,
                             const float* __restrict__ linb,
                             float* __restrict__ out)
{
    __shared__ float As[32][64];    // [k][m]
    __shared__ float Bs[32][64];    // [k][n]
    const int tid = threadIdx.x;
    const int tx = tid & 15;
    const int ty = tid >> 4;
    const int bm = blockIdx.x * 64;

    unsigned long long acc2[4][2];
#pragma unroll
    for (int i = 0; i < 4; ++i) { acc2[i][0] = 0ull; acc2[i][1] = 0ull; }

    for (int k0 = 0; k0 < HC; k0 += 32) {
#pragma unroll
        for (int r = 0; r < 2; ++r) {
            int idx = tid + r * 256;
            int row = idx >> 3;
            int kk4 = idx & 7;
            int gm = bm + row;
            float4 v = make_float4(0.f, 0.f, 0.f, 0.f);
            if (gm < NN)
                v = *reinterpret_cast<const float4*>(g_z + (size_t)gm * HC + k0 + kk4 * 4);
            As[kk4 * 4 + 0][row] = v.x;
            As[kk4 * 4 + 1][row] = v.y;
            As[kk4 * 4 + 2][row] = v.z;
            As[kk4 * 4 + 3][row] = v.w;
        }
#pragma unroll
        for (int r = 0; r < 2; ++r) {
            int idx = tid + r * 256;
            int kk = idx >> 4;
            int nn4 = idx & 15;
            *reinterpret_cast<float4*>(&Bs[kk][nn4 * 4]) =
                *reinterpret_cast<const float4*>(linW + (size_t)(k0 + kk) * OUT_DIM + nn4 * 4);
        }
        __syncthreads();
#pragma unroll
        for (int k = 0; k < 32; ++k) {
            float4 av = reinterpret_cast<const float4*>(&As[k][0])[ty];
            float4 bv = reinterpret_cast<const float4*>(&Bs[k][0])[tx];
            unsigned long long b01 = pack2(bv.x, bv.y);
            unsigned long long b23 = pack2(bv.z, bv.w);
            float a[4] = {av.x, av.y, av.z, av.w};
#pragma unroll
            for (int i = 0; i < 4; ++i) {
                unsigned long long ai = pack2(a[i], a[i]);
                acc2[i][0] = ffma2(ai, b01, acc2[i][0]);
                acc2[i][1] = ffma2(ai, b23, acc2[i][1]);
            }
        }
        __syncthreads();
    }
    float4 bb = *reinterpret_cast<const float4*>(linb + tx * 4);
#pragma unroll
    for (int i = 0; i < 4; ++i) {
        int gm = bm + ty * 4 + i;
        if (gm < NN) {
            float4 o;
            unpack2(acc2[i][0], o.x, o.y);
            unpack2(acc2[i][1], o.z, o.w);
            o.x += bb.x; o.y += bb.y; o.z += bb.z; o.w += bb.w;
            *reinterpret_cast<float4*>(out + (size_t)gm * OUT_DIM + tx * 4) = o;
        }
    }
}

// ---------------- launch ------------------------------------------------------
extern "C" void kernel_launch(void* const* d_in, const int* in_sizes, int n_in,
                              void* d_out, int out_size)
{
    const float* x        = (const float*)d_in[0];
    const void*  ei       = (const void*)d_in[1];
    const float* W        = (const float*)d_in[2];
    const float* att_src  = (const float*)d_in[3];
    const float* att_dst  = (const float*)d_in[4];
    const float* bias     = (const float*)d_in[5];
    const float* lin_W    = (const float*)d_in[6];
    const float* lin_b    = (const float*)d_in[7];
    float* out            = (float*)d_out;

    const int warp_blocks = (NN * 32 + 255) / 256;   // 6250
    const int gemm_blocks = (NN + 63) / 64;          // 782

    fused1_kernel<<<G1BLK + HISTBLK, 256>>>(x, W, ei);             // launch 0
    scan1_kernel<<<SCAN_NBLK, 1024>>>();                           // launch 1
    scan3_kernel<<<SCAN_NBLK, 1024>>>();                           // launch 2
    fused3_kernel<<<SCATBLK + ATTNBLK, 256>>>(ei, att_src, att_dst); // launch 3
    agg_kernel<<<warp_blocks, 256>>>(bias);                        // launch 4
    gemm2_kernel<<<gemm_blocks, 256>>>(lin_W, lin_b, out);         // launch 5
}

// round 15
// speedup vs baseline: 1.8986x; 1.1522x over previous
#include <cuda_runtime.h>
#include <cuda_fp16.h>
#include <cstdint>

// Problem constants (fixed shapes)
#define NN 50000
#define EE 1600000
#define IN_DIM 256
#define HC 128          // H*C = 4*32
#define OUT_DIM 64
#define NEG_SLOPE 0.2f
#define SCAN_NBLK 49    // ceil(50000/1024)
#define G1HBLK 391      // gemm1 HMMA blocks (ceil(50000/128))
#define HISTB 782       // hist blocks, 2048 edges each (grid-stride x8)
#define SCATBLK 6250    // scatter blocks (EE/256)
#define ATTNBLK 6250    // attn blocks   (50000 nodes @8 warps/blk)

// SMEM layout for fused1 gemm path
#define SA_LD 136       // 128 + 8 pad (halves)
#define SWT_LD 264      // 256 + 8 pad (halves)
#define SMEM_SA_BYTES (128 * SA_LD * 2)            // 34816
#define SMEM_F1 (SMEM_SA_BYTES + 128 * SWT_LD * 2) // 34816 + 67584 = 102400

// ---------------- scratch (__device__ globals; no allocation allowed) -------
// NOTE: g_cnt is self-restoring: hist does +1 per (valid-d) edge, scatter does
// -1 per (valid-d) edge => returns to all-zero after every full run. No memset.
__device__ float  g_h[(size_t)NN * HC];    // x @ W (fp32)
__device__ __half g_h16[(size_t)NN * HC];  // fp16 shadow for the gather path
__device__ float  g_asrc[NN * 4];
__device__ float  g_adst[NN * 4];
__device__ float  g_z[(size_t)NN * HC];    // elu(agg + bias)
__device__ int    g_cnt[NN];               // zero-init at load; self-restoring
__device__ int    g_off[NN + 1];
__device__ int    g_bsum[64];
__device__ int    g_srcsorted[EE];

// ---------------- f32x2 packed FMA helpers (sm_103a FFMA2) -------------------
__device__ __forceinline__ unsigned long long pack2(float lo, float hi)
{
    unsigned long long r;
    asm("mov.b64 %0, {%1, %2};" : "=l"(r) : "f"(lo), "f"(hi));
    return r;
}
__device__ __forceinline__ void unpack2(unsigned long long v, float& lo, float& hi)
{
    asm("mov.b64 {%0, %1}, %2;" : "=f"(lo), "=f"(hi) : "l"(v));
}
__device__ __forceinline__ unsigned long long ffma2(unsigned long long a,
                                                    unsigned long long b,
                                                    unsigned long long c)
{
    unsigned long long d;
    asm("fma.rn.f32x2 %0, %1, %2, %3;" : "=l"(d) : "l"(a), "l"(b), "l"(c));
    return d;
}

// ---------------- HMMA helpers -----------------------------------------------
__device__ __forceinline__ void mma16816(float* d,
    uint32_t a0, uint32_t a1, uint32_t a2, uint32_t a3,
    uint32_t b0, uint32_t b1)
{
    asm volatile(
        "mma.sync.aligned.m16n8k16.row.col.f32.f16.f16.f32 "
        "{%0,%1,%2,%3}, {%4,%5,%6,%7}, {%8,%9}, {%0,%1,%2,%3};"
        : "+f"(d[0]), "+f"(d[1]), "+f"(d[2]), "+f"(d[3])
        : "r"(a0), "r"(a1), "r"(a2), "r"(a3), "r"(b0), "r"(b1));
}

// ---------------- per-block edge dtype detection ------------------------------
// int64 little-endian values < 2^31: odd int32 words are all zero.
__device__ __forceinline__ int block_detect_is64(const int* __restrict__ ei32)
{
    int any = 0;
    if (threadIdx.x < 64) any = ei32[2 * threadIdx.x + 1];
    return __syncthreads_or(any) ? 0 : 1;
}

__device__ __forceinline__ int load_edge(const void* ei, size_t idx, int is64)
{
    if (is64) return (int)((const long long*)ei)[idx];
    return ((const int*)ei)[idx];
}

// ---------------- fused1: gemm1 HMMA tiles  ||  hist --------------------------
// gemm path: BM=128 (8 warps x m16 strips), N=128, K=256 (two K-halves staged).
// A (x) converted fp32->fp16 into sA; W converted+transposed into sWt once.
__global__ void __launch_bounds__(256) fused1_kernel(const float* __restrict__ x,
                                                     const float* __restrict__ W,
                                                     const void* __restrict__ ei)
{
    if (blockIdx.x >= G1HBLK) {
        // ---- hist path: 2048 edges per block ----
        int is64 = block_detect_is64((const int*)ei);
        int base = (blockIdx.x - G1HBLK) * 2048 + threadIdx.x;
#pragma unroll
        for (int i = 0; i < 8; ++i) {
            int e = base + i * 256;
            if (e < EE) {
                int d = load_edge(ei, (size_t)EE + e, is64);
                if ((unsigned)d < NN) atomicAdd(&g_cnt[d], 1);
            }
        }
        return;
    }
    // ---- gemm1 HMMA path ----
    extern __shared__ char smem[];
    __half* sA  = reinterpret_cast<__half*>(smem);                  // [128][SA_LD]
    __half* sWt = reinterpret_cast<__half*>(smem + SMEM_SA_BYTES);  // [128][SWT_LD] (n-major)

    const int tid  = threadIdx.x;
    const int lane = tid & 31;
    const int wm   = tid >> 5;           // warp id 0..7 -> rows wm*16..+15
    const int bm   = blockIdx.x * 128;
    const int tig  = lane & 3;           // thread in group
    const int g    = lane >> 2;          // group id

    // Load + transpose W (256x128 fp32) -> sWt[n][k] fp16. One time.
    // idx over (k-pair, n): 128 pairs x 128 n = 16384 entries, 64 per thread.
#pragma unroll
    for (int it = 0; it < 64; ++it) {
        int idx = tid + it * 256;
        int n   = idx & 127;
        int k2  = idx >> 7;              // 0..127
        float w0 = W[(size_t)(2 * k2) * HC + n];
        float w1 = W[(size_t)(2 * k2 + 1) * HC + n];
        *reinterpret_cast<__half2*>(&sWt[n * SWT_LD + 2 * k2]) =
            __floats2half2_rn(w0, w1);
    }

    float d[16][4];
#pragma unroll
    for (int at = 0; at < 16; ++at)
#pragma unroll
        for (int q = 0; q < 4; ++q) d[at][q] = 0.f;

    for (int half = 0; half < 2; ++half) {
        if (half) __syncthreads();
        // Load x tile rows bm..bm+127, k in [half*128, half*128+128) -> sA fp16
        // idx over (row, col-pair): 128 rows x 64 pairs = 8192, 32 per thread.
#pragma unroll
        for (int it = 0; it < 32; ++it) {
            int idx  = tid + it * 256;
            int colp = idx & 63;         // float2 index within 128 cols
            int row  = idx >> 6;
            int gm   = bm + row;
            float2 v = make_float2(0.f, 0.f);
            if (gm < NN)
                v = *reinterpret_cast<const float2*>(
                    x + (size_t)gm * IN_DIM + half * 128 + colp * 2);
            *reinterpret_cast<__half2*>(&sA[row * SA_LD + colp * 2]) =
                __floats2half2_rn(v.x, v.y);
        }
        __syncthreads();

#pragma unroll
        for (int kc = 0; kc < 8; ++kc) {
            // A fragment via ldmatrix.x4
            int r  = wm * 16 + (lane & 15);
            int kk = kc * 16 + (lane >> 4) * 8;
            uint32_t saddr = (uint32_t)__cvta_generic_to_shared(&sA[r * SA_LD + kk]);
            uint32_t a0, a1, a2, a3;
            asm volatile(
                "ldmatrix.sync.aligned.m8n8.x4.shared.b16 {%0,%1,%2,%3}, [%4];"
                : "=r"(a0), "=r"(a1), "=r"(a2), "=r"(a3) : "r"(saddr));

            int kbase = (half * 8 + kc) * 16 + tig * 2;
#pragma unroll
            for (int at = 0; at < 16; ++at) {
                int n = at * 8 + g;
                uint32_t b0 = *reinterpret_cast<const uint32_t*>(&sWt[n * SWT_LD + kbase]);
                uint32_t b1 = *reinterpret_cast<const uint32_t*>(&sWt[n * SWT_LD + kbase + 8]);
                mma16816(d[at], a0, a1, a2, a3, b0, b1);
            }
        }
    }

    // Store D -> g_h (fp32) + g_h16 (fp16 shadow)
    int r0w = bm + wm * 16 + g;
    int r1w = r0w + 8;
#pragma unroll
    for (int at = 0; at < 16; ++at) {
        int col = at * 8 + tig * 2;
        if (r0w < NN) {
            *reinterpret_cast<float2*>(g_h + (size_t)r0w * HC + col) =
                make_float2(d[at][0], d[at][1]);
            *reinterpret_cast<__half2*>(g_h16 + (size_t)r0w * HC + col) =
                __floats2half2_rn(d[at][0], d[at][1]);
        }
        if (r1w < NN) {
            *reinterpret_cast<float2*>(g_h + (size_t)r1w * HC + col) =
                make_float2(d[at][2], d[at][3]);
            *reinterpret_cast<__half2*>(g_h16 + (size_t)r1w * HC + col) =
                __floats2half2_rn(d[at][2], d[at][3]);
        }
    }
}

// ---------------- scan1: per-block inclusive scan of g_cnt --------------------
__global__ void scan1_kernel()
{
    __shared__ int wsum[32];
    int t = threadIdx.x;
    int lane = t & 31;
    int wid = t >> 5;
    int i = blockIdx.x * 1024 + t;
    int v = (i < NN) ? g_cnt[i] : 0;
    int sc = v;
#pragma unroll
    for (int off = 1; off < 32; off <<= 1) {
        int n = __shfl_up_sync(0xFFFFFFFFu, sc, off);
        if (lane >= off) sc += n;
    }
    if (lane == 31) wsum[wid] = sc;
    __syncthreads();
    if (wid == 0) {
        int ws = wsum[lane];
#pragma unroll
        for (int off = 1; off < 32; off <<= 1) {
            int n = __shfl_up_sync(0xFFFFFFFFu, ws, off);
            if (lane >= off) ws += n;
        }
        wsum[lane] = ws;
    }
    __syncthreads();
    int base = (wid > 0) ? wsum[wid - 1] : 0;
    int inc = base + sc;
    if (i < NN) g_off[i + 1] = inc;
    if (t == 1023) g_bsum[blockIdx.x] = inc;
}

// ---------------- scan3: add cross-block prefix -------------------------------
__global__ void scan3_kernel()
{
    __shared__ int s_pref;
    if (threadIdx.x == 0) {
        int acc = 0;
        for (int b = 0; b < (int)blockIdx.x; ++b) acc += g_bsum[b];
        s_pref = acc;
    }
    __syncthreads();
    int i = blockIdx.x * 1024 + threadIdx.x;
    if (i < NN) g_off[i + 1] += s_pref;
    if (i == 0) g_off[0] = 0;
}

// ---------------- fused3: scatter  ||  attn_halves ----------------------------
__global__ void fused3_kernel(const void* __restrict__ ei,
                              const float* __restrict__ att_src,
                              const float* __restrict__ att_dst)
{
    if (blockIdx.x < SCATBLK) {
        // ---- scatter path ----
        int is64 = block_detect_is64((const int*)ei);
        int e = blockIdx.x * 256 + threadIdx.x;
        if (e < EE) {
            int d = load_edge(ei, (size_t)EE + e, is64);
            int s = load_edge(ei, (size_t)e, is64);
            if ((unsigned)d < NN) {                 // decrement matches hist exactly
                int rem = atomicSub(&g_cnt[d], 1);  // old count
                int pos = g_off[d] + rem - 1;
                if ((unsigned)s < NN && (unsigned)pos < EE) g_srcsorted[pos] = s;
            }
        }
        return;
    }
    // ---- attn path ----
    int w = (blockIdx.x - SCATBLK) * 8 + (threadIdx.x >> 5);
    int lane = threadIdx.x & 31;
    if (w >= NN) return;
    float4 hv = *reinterpret_cast<const float4*>(g_h + (size_t)w * HC + lane * 4);
    float4 s4 = *reinterpret_cast<const float4*>(att_src + lane * 4);
    float4 d4 = *reinterpret_cast<const float4*>(att_dst + lane * 4);
    float ps = hv.x * s4.x + hv.y * s4.y + hv.z * s4.z + hv.w * s4.w;
    float pd = hv.x * d4.x + hv.y * d4.y + hv.z * d4.z + hv.w * d4.w;
#pragma unroll
    for (int off = 1; off < 8; off <<= 1) {
        ps += __shfl_xor_sync(0xFFFFFFFFu, ps, off);
        pd += __shfl_xor_sync(0xFFFFFFFFu, pd, off);
    }
    float4 po, qo;
    po.x = __shfl_sync(0xFFFFFFFFu, ps, 0);
    po.y = __shfl_sync(0xFFFFFFFFu, ps, 8);
    po.z = __shfl_sync(0xFFFFFFFFu, ps, 16);
    po.w = __shfl_sync(0xFFFFFFFFu, ps, 24);
    qo.x = __shfl_sync(0xFFFFFFFFu, pd, 0);
    qo.y = __shfl_sync(0xFFFFFFFFu, pd, 8);
    qo.z = __shfl_sync(0xFFFFFFFFu, pd, 16);
    qo.w = __shfl_sync(0xFFFFFFFFu, pd, 24);
    if (lane == 0) {
        *reinterpret_cast<float4*>(g_asrc + w * 4) = po;
        *reinterpret_cast<float4*>(g_adst + w * 4) = qo;
    }
}

// ---------------- aggregation: warp per dst node, 16-edge batches -------------
__global__ void __launch_bounds__(256) agg_kernel(const float* __restrict__ bias)
{
    int w = (blockIdx.x * blockDim.x + threadIdx.x) >> 5;
    int lane = threadIdx.x & 31;
    if (w >= NN) return;
    const int kl = lane & 3;
    const int j  = lane >> 2;
    const int kh = lane >> 3;

    float adv_l = g_adst[w * 4 + kl];
    float asl_l = g_asrc[w * 4 + kl];
    float adv_a = g_adst[w * 4 + kh];
    float asl_a = g_asrc[w * 4 + kh];

    float e0l = asl_l + adv_l;
    e0l = (e0l > 0.f) ? e0l : NEG_SLOPE * e0l;
    float dnm = (j == 0) ? __expf(e0l) : 0.f;

    float e0a = asl_a + adv_a;
    e0a = (e0a > 0.f) ? e0a : NEG_SLOPE * e0a;
    float pe0a = __expf(e0a);
    float4 hw = *reinterpret_cast<const float4*>(g_h + (size_t)w * HC + lane * 4);
    float4 acc;
    acc.x = pe0a * hw.x; acc.y = pe0a * hw.y;
    acc.z = pe0a * hw.z; acc.w = pe0a * hw.w;

    const int beg = g_off[w];
    const int end = g_off[w + 1];
    int p = beg;

    for (; p + 16 <= end; p += 16) {
        int s0 = g_srcsorted[p + j];
        int s1 = g_srcsorted[p + 8 + j];
        float as0 = __ldg(g_asrc + (size_t)s0 * 4 + kl);
        float as1 = __ldg(g_asrc + (size_t)s1 * 4 + kl);
        float ea = as0 + adv_l;
        ea = (ea > 0.f) ? ea : NEG_SLOPE * ea;
        float eb = as1 + adv_l;
        eb = (eb > 0.f) ? eb : NEG_SLOPE * eb;
        float pe0 = __expf(ea);
        float pe1 = __expf(eb);
        dnm += pe0 + pe1;
        int sj[16];
#pragma unroll
        for (int jj = 0; jj < 8; ++jj) {
            sj[jj]     = __shfl_sync(0xFFFFFFFFu, s0, jj * 4);
            sj[8 + jj] = __shfl_sync(0xFFFFFFFFu, s1, jj * 4);
        }
        __half2 h01[16], h23[16];
#pragma unroll
        for (int jj = 0; jj < 16; ++jj) {
            const __half2* hp = reinterpret_cast<const __half2*>(
                g_h16 + (size_t)sj[jj] * HC + lane * 4);
            h01[jj] = __ldg(hp + 0);
            h23[jj] = __ldg(hp + 1);
        }
#pragma unroll
        for (int jj = 0; jj < 8; ++jj) {
            float q0 = __shfl_sync(0xFFFFFFFFu, pe0, jj * 4 + kh);
            float2 f01 = __half22float2(h01[jj]);
            float2 f23 = __half22float2(h23[jj]);
            acc.x = fmaf(q0, f01.x, acc.x);
            acc.y = fmaf(q0, f01.y, acc.y);
            acc.z = fmaf(q0, f23.x, acc.z);
            acc.w = fmaf(q0, f23.y, acc.w);
        }
#pragma unroll
        for (int jj = 0; jj < 8; ++jj) {
            float q1 = __shfl_sync(0xFFFFFFFFu, pe1, jj * 4 + kh);
            float2 f01 = __half22float2(h01[8 + jj]);
            float2 f23 = __half22float2(h23[8 + jj]);
            acc.x = fmaf(q1, f01.x, acc.x);
            acc.y = fmaf(q1, f01.y, acc.y);
            acc.z = fmaf(q1, f23.x, acc.z);
            acc.w = fmaf(q1, f23.y, acc.w);
        }
    }

    if (p + 8 <= end) {
        int s = g_srcsorted[p + j];
        float as = __ldg(g_asrc + (size_t)s * 4 + kl);
        float e = as + adv_l;
        e = (e > 0.f) ? e : NEG_SLOPE * e;
        float pe = __expf(e);
        dnm += pe;
        int   sj[8];
        float q[8];
#pragma unroll
        for (int jj = 0; jj < 8; ++jj) {
            sj[jj] = __shfl_sync(0xFFFFFFFFu, s,  jj * 4);
            q[jj]  = __shfl_sync(0xFFFFFFFFu, pe, jj * 4 + kh);
        }
        __half2 h01[8], h23[8];
#pragma unroll
        for (int jj = 0; jj < 8; ++jj) {
            const __half2* hp = reinterpret_cast<const __half2*>(
                g_h16 + (size_t)sj[jj] * HC + lane * 4);
            h01[jj] = __ldg(hp + 0);
            h23[jj] = __ldg(hp + 1);
        }
#pragma unroll
        for (int jj = 0; jj < 8; ++jj) {
            float2 f01 = __half22float2(h01[jj]);
            float2 f23 = __half22float2(h23[jj]);
            acc.x = fmaf(q[jj], f01.x, acc.x);
            acc.y = fmaf(q[jj], f01.y, acc.y);
            acc.z = fmaf(q[jj], f23.x, acc.z);
            acc.w = fmaf(q[jj], f23.y, acc.w);
        }
        p += 8;
    }

    if (p < end) {
        int cnt = end - p;
        int ridx = p + ((j < cnt) ? j : (cnt - 1));
        int s = g_srcsorted[ridx];
        float as = __ldg(g_asrc + (size_t)s * 4 + kl);
        float e = as + adv_l;
        e = (e > 0.f) ? e : NEG_SLOPE * e;
        float pe = (j < cnt) ? __expf(e) : 0.f;
        dnm += pe;
        for (int jj = 0; jj < cnt; ++jj) {
            int   sj = __shfl_sync(0xFFFFFFFFu, s,  jj * 4);
            float qv = __shfl_sync(0xFFFFFFFFu, pe, jj * 4 + kh);
            const __half2* hp = reinterpret_cast<const __half2*>(
                g_h16 + (size_t)sj * HC + lane * 4);
            __half2 a01 = __ldg(hp + 0);
            __half2 a23 = __ldg(hp + 1);
            float2 f01 = __half22float2(a01);
            float2 f23 = __half22float2(a23);
            acc.x = fmaf(qv, f01.x, acc.x);
            acc.y = fmaf(qv, f01.y, acc.y);
            acc.z = fmaf(qv, f23.x, acc.z);
            acc.w = fmaf(qv, f23.y, acc.w);
        }
    }

    dnm += __shfl_xor_sync(0xFFFFFFFFu, dnm, 4);
    dnm += __shfl_xor_sync(0xFFFFFFFFu, dnm, 8);
    dnm += __shfl_xor_sync(0xFFFFFFFFu, dnm, 16);
    float dn = __shfl_sync(0xFFFFFFFFu, dnm, kh);
    float inv = 1.f / dn;

    float4 bb = *reinterpret_cast<const float4*>(bias + lane * 4);
    float4 r;
    r.x = acc.x * inv + bb.x;
    r.y = acc.y * inv + bb.y;
    r.z = acc.z * inv + bb.z;
    r.w = acc.w * inv + bb.w;
    r.x = (r.x > 0.f) ? r.x : (__expf(r.x) - 1.f);
    r.y = (r.y > 0.f) ? r.y : (__expf(r.y) - 1.f);
    r.z = (r.z > 0.f) ? r.z : (__expf(r.z) - 1.f);
    r.w = (r.w > 0.f) ? r.w : (__expf(r.w) - 1.f);
    *reinterpret_cast<float4*>(g_z + (size_t)w * HC + lane * 4) = r;
}

// ---------------- GEMM2: out = z @ lin_W + lin_b  (50000x128 * 128x64) -------
// BM=64, BN=64, BK=32, 256 threads, dup-A FFMA2 (known-good form)
__global__ void gemm2_kernel(const float* __restrict__ linW,
                             const float* __restrict__ linb,
                             float* __restrict__ out)
{
    __shared__ float As[32][64];    // [k][m]
    __shared__ float Bs[32][64];    // [k][n]
    const int tid = threadIdx.x;
    const int tx = tid & 15;
    const int ty = tid >> 4;
    const int bm = blockIdx.x * 64;

    unsigned long long acc2[4][2];
#pragma unroll
    for (int i = 0; i < 4; ++i) { acc2[i][0] = 0ull; acc2[i][1] = 0ull; }

    for (int k0 = 0; k0 < HC; k0 += 32) {
#pragma unroll
        for (int r = 0; r < 2; ++r) {
            int idx = tid + r * 256;
            int row = idx >> 3;
            int kk4 = idx & 7;
            int gm = bm + row;
            float4 v = make_float4(0.f, 0.f, 0.f, 0.f);
            if (gm < NN)
                v = *reinterpret_cast<const float4*>(g_z + (size_t)gm * HC + k0 + kk4 * 4);
            As[kk4 * 4 + 0][row] = v.x;
            As[kk4 * 4 + 1][row] = v.y;
            As[kk4 * 4 + 2][row] = v.z;
            As[kk4 * 4 + 3][row] = v.w;
        }
#pragma unroll
        for (int r = 0; r < 2; ++r) {
            int idx = tid + r * 256;
            int kk = idx >> 4;
            int nn4 = idx & 15;
            *reinterpret_cast<float4*>(&Bs[kk][nn4 * 4]) =
                *reinterpret_cast<const float4*>(linW + (size_t)(k0 + kk) * OUT_DIM + nn4 * 4);
        }
        __syncthreads();
#pragma unroll
        for (int k = 0; k < 32; ++k) {
            float4 av = reinterpret_cast<const float4*>(&As[k][0])[ty];
            float4 bv = reinterpret_cast<const float4*>(&Bs[k][0])[tx];
            unsigned long long b01 = pack2(bv.x, bv.y);
            unsigned long long b23 = pack2(bv.z, bv.w);
            float a[4] = {av.x, av.y, av.z, av.w};
#pragma unroll
            for (int i = 0; i < 4; ++i) {
                unsigned long long ai = pack2(a[i], a[i]);
                acc2[i][0] = ffma2(ai, b01, acc2[i][0]);
                acc2[i][1] = ffma2(ai, b23, acc2[i][1]);
            }
        }
        __syncthreads();
    }
    float4 bb = *reinterpret_cast<const float4*>(linb + tx * 4);
#pragma unroll
    for (int i = 0; i < 4; ++i) {
        int gm = bm + ty * 4 + i;
        if (gm < NN) {
            float4 o;
            unpack2(acc2[i][0], o.x, o.y);
            unpack2(acc2[i][1], o.z, o.w);
            o.x += bb.x; o.y += bb.y; o.z += bb.z; o.w += bb.w;
            *reinterpret_cast<float4*>(out + (size_t)gm * OUT_DIM + tx * 4) = o;
        }
    }
}

// ---------------- launch ------------------------------------------------------
extern "C" void kernel_launch(void* const* d_in, const int* in_sizes, int n_in,
                              void* d_out, int out_size)
{
    const float* x        = (const float*)d_in[0];
    const void*  ei       = (const void*)d_in[1];
    const float* W        = (const float*)d_in[2];
    const float* att_src  = (const float*)d_in[3];
    const float* att_dst  = (const float*)d_in[4];
    const float* bias     = (const float*)d_in[5];
    const float* lin_W    = (const float*)d_in[6];
    const float* lin_b    = (const float*)d_in[7];
    float* out            = (float*)d_out;

    const int warp_blocks = (NN * 32 + 255) / 256;   // 6250
    const int gemm_blocks = (NN + 63) / 64;          // 782

    cudaFuncSetAttribute(fused1_kernel,
                         cudaFuncAttributeMaxDynamicSharedMemorySize, SMEM_F1);

    fused1_kernel<<<G1HBLK + HISTB, 256, SMEM_F1>>>(x, W, ei);       // launch 0
    scan1_kernel<<<SCAN_NBLK, 1024>>>();                             // launch 1
    scan3_kernel<<<SCAN_NBLK, 1024>>>();                             // launch 2
    fused3_kernel<<<SCATBLK + ATTNBLK, 256>>>(ei, att_src, att_dst); // launch 3
    agg_kernel<<<warp_blocks, 256>>>(bias);                          // launch 4
    gemm2_kernel<<<gemm_blocks, 256>>>(lin_W, lin_b, out);           // launch 5
}